// round 5
// baseline (speedup 1.0000x reference)
#include <cuda_runtime.h>

// Problem constants
#define S_   1024
#define B_   8
#define D_   1024
#define H_   16
#define HD_  64
#define T_   (B_ * S_)
#define D3_  (3 * D_)

// Scratch
__device__ float g_qkv[(size_t)T_ * 3 * D_];
__device__ float g_attn[(size_t)T_ * D_];
__device__ float g_attnout[(size_t)T_ * D_];
__device__ float g_linv[B_ * H_ * S_];
__device__ float g_xr[(size_t)T_ * D_];      // tf32-rounded x
__device__ float g_wi[(size_t)D3_ * D_];     // tf32-rounded in_proj_w
__device__ float g_wo[(size_t)D_ * D_];      // tf32-rounded out_proj_w

__device__ __forceinline__ unsigned su32(const void* p) {
    return (unsigned)__cvta_generic_to_shared(p);
}
__device__ __forceinline__ void cpa16(unsigned dst, const float* src) {
    asm volatile("cp.async.cg.shared.global [%0], [%1], 16;" :: "r"(dst), "l"(src));
}
#define CP_COMMIT() asm volatile("cp.async.commit_group;")
#define CP_WAIT0()  asm volatile("cp.async.wait_group 0;")
#define CP_WAIT2()  asm volatile("cp.async.wait_group 2;")

__device__ __forceinline__ float f2tf(float x) {
    unsigned r;
    asm("cvt.rna.tf32.f32 %0, %1;" : "=r"(r) : "f"(x));
    return __uint_as_float(r);
}
__device__ __forceinline__ unsigned ftou(float x) { return __float_as_uint(x); }

__device__ __forceinline__ void mma8(float* d, const unsigned* a, const unsigned* b) {
    asm volatile(
        "mma.sync.aligned.m16n8k8.row.col.f32.tf32.tf32.f32 "
        "{%0,%1,%2,%3},{%4,%5,%6,%7},{%8,%9},{%0,%1,%2,%3};"
        : "+f"(d[0]), "+f"(d[1]), "+f"(d[2]), "+f"(d[3])
        : "r"(a[0]), "r"(a[1]), "r"(a[2]), "r"(a[3]), "r"(b[0]), "r"(b[1]));
}

// ---------------------------------------------------------------------------
// Elementwise tf32 rounding (float4 grid-stride)
// ---------------------------------------------------------------------------
__global__ void __launch_bounds__(256) round_tf32_kernel(
    const float* __restrict__ src, float* __restrict__ dst, int n4)
{
    int i = blockIdx.x * blockDim.x + threadIdx.x;
    if (i < n4) {
        float4 v = ((const float4*)src)[i];
        v.x = f2tf(v.x); v.y = f2tf(v.y); v.z = f2tf(v.z); v.w = f2tf(v.w);
        ((float4*)dst)[i] = v;
    }
}

// ---------------------------------------------------------------------------
// tf32 GEMM, cp.async 3-stage. Inputs MUST be pre-rounded tf32 values.
// C[M,N] = A[M,K] @ B[N,K]^T + bias[N]. ROUND_OUT rounds C to tf32.
// ---------------------------------------------------------------------------
#define GST 20
template<bool ROUND_OUT>
__global__ void __launch_bounds__(256) gemm_tf32_kernel(
    const float* __restrict__ A, const float* __restrict__ Bm,
    const float* __restrict__ bias, float* __restrict__ C,
    int M, int N, int K)
{
    extern __shared__ float sm[];
    float* Asm = sm;
    float* Bsm = sm + 3 * 128 * GST;

    const int tid  = threadIdx.x;
    const int lane = tid & 31;
    const int wid  = tid >> 5;
    const int wm   = wid & 1;
    const int wn   = wid >> 1;
    const int m0 = blockIdx.y * 128;
    const int n0 = blockIdx.x * 128;
    const int lr  = tid >> 1;
    const int lk8 = (tid & 1) * 8;
    const float* Ap = A  + (size_t)(m0 + lr) * K + lk8;
    const float* Bp = Bm + (size_t)(n0 + lr) * K + lk8;
    const int gid = lane >> 2;
    const int tig = lane & 3;

    auto issue = [&](int st, int k0) {
        float* Ad = Asm + st * (128 * GST) + lr * GST + lk8;
        float* Bd = Bsm + st * (128 * GST) + lr * GST + lk8;
        cpa16(su32(Ad),     Ap + k0);
        cpa16(su32(Ad + 4), Ap + k0 + 4);
        cpa16(su32(Bd),     Bp + k0);
        cpa16(su32(Bd + 4), Bp + k0 + 4);
        CP_COMMIT();
    };

    float acc[4][4][4];
#pragma unroll
    for (int i = 0; i < 4; i++)
#pragma unroll
        for (int j = 0; j < 4; j++)
#pragma unroll
            for (int r = 0; r < 4; r++) acc[i][j][r] = 0.f;

    issue(0, 0); issue(1, 16); issue(2, 32);

    const int NIT = K / 16;
    int st = 0;
    for (int i = 0; i < NIT; i++) {
        CP_WAIT2();
        __syncthreads();
        const float* Ac = Asm + st * (128 * GST);
        const float* Bc = Bsm + st * (128 * GST);
#pragma unroll
        for (int ks = 0; ks < 16; ks += 8) {
            unsigned af[4][4], bf[4][2];
#pragma unroll
            for (int mi = 0; mi < 4; mi++) {
                int m = wm * 64 + mi * 16 + gid;
                af[mi][0] = ftou(Ac[m * GST + ks + tig]);
                af[mi][1] = ftou(Ac[(m + 8) * GST + ks + tig]);
                af[mi][2] = ftou(Ac[m * GST + ks + 4 + tig]);
                af[mi][3] = ftou(Ac[(m + 8) * GST + ks + 4 + tig]);
            }
#pragma unroll
            for (int ni = 0; ni < 4; ni++) {
                int n = wn * 32 + ni * 8 + gid;
                bf[ni][0] = ftou(Bc[n * GST + ks + tig]);
                bf[ni][1] = ftou(Bc[n * GST + ks + 4 + tig]);
            }
#pragma unroll
            for (int mi = 0; mi < 4; mi++)
#pragma unroll
                for (int ni = 0; ni < 4; ni++)
                    mma8(acc[mi][ni], af[mi], bf[ni]);
        }
        __syncthreads();
        if (i + 3 < NIT) issue(st, (i + 3) * 16);
        st = (st == 2) ? 0 : st + 1;
    }

#pragma unroll
    for (int mi = 0; mi < 4; mi++) {
        int m = m0 + wm * 64 + mi * 16 + gid;
#pragma unroll
        for (int ni = 0; ni < 4; ni++) {
            int n = n0 + wn * 32 + ni * 8 + 2 * tig;
            float bx = bias[n], by = bias[n + 1];
            float2 o0, o1;
            if (ROUND_OUT) {
                o0 = make_float2(f2tf(acc[mi][ni][0] + bx), f2tf(acc[mi][ni][1] + by));
                o1 = make_float2(f2tf(acc[mi][ni][2] + bx), f2tf(acc[mi][ni][3] + by));
            } else {
                o0 = make_float2(acc[mi][ni][0] + bx, acc[mi][ni][1] + by);
                o1 = make_float2(acc[mi][ni][2] + bx, acc[mi][ni][3] + by);
            }
            *(float2*)(C + (size_t)m * N + n) = o0;
            *(float2*)(C + (size_t)(m + 8) * N + n) = o1;
        }
    }
}

// ---------------------------------------------------------------------------
// Flash attention, tensor-core, NO online max (scores bounded: exp is safe).
// Block = (b*h, q-tile of 128), 256 thr (8 warps). lsum reduced in epilogue.
// ---------------------------------------------------------------------------
__global__ void __launch_bounds__(256) flash_kernel(const float* __restrict__ td_ptr)
{
    extern __shared__ float sm[];
    float* Qs  = sm;            // 8192
    float* Ksb = sm + 8192;     // 2 x 4096
    float* Vsb = sm + 16384;    // 2 x 4096
    float* Psb = sm + 24576;    // 8 x 1056

    const int tid  = threadIdx.x;
    const int lane = tid & 31;
    const int w    = tid >> 5;
    const int gid  = lane >> 2;
    const int tig  = lane & 3;
    const int bh = blockIdx.x;
    const int qt = blockIdx.y;
    const int b  = bh >> 4;
    const int h  = bh & 15;
    const float atd = fabsf(*td_ptr);
    const float scale = 0.125f;

    {
        const float* qb = g_qkv + (size_t)(b * S_ + qt * 128) * D3_ + h * HD_;
#pragma unroll
        for (int l = 0; l < 8; l++) {
            int lin = tid + l * 256;
            int r = lin >> 4;
            int u = lin & 15;
            cpa16(su32(&Qs[r * 64 + ((4 * u) ^ (4 * (r & 7)))]),
                  qb + (size_t)r * D3_ + u * 4);
        }
    }
    auto issueKV = [&](int kt, int bf) {
        const float* kb = g_qkv + (size_t)(b * S_ + kt * 64) * D3_ + D_ + h * HD_;
        const float* vb = kb + D_;
        float* Kd = Ksb + bf * 4096;
        float* Vd = Vsb + bf * 4096;
#pragma unroll
        for (int l = 0; l < 4; l++) {
            int lin = tid + l * 256;
            int r = lin >> 4;
            int u = lin & 15;
            cpa16(su32(&Kd[r * 64 + ((4 * u) ^ (4 * (r & 7)))]), kb + (size_t)r * D3_ + u * 4);
            cpa16(su32(&Vd[r * 64 + ((4 * u) ^ (8 * (r & 3)))]), vb + (size_t)r * D3_ + u * 4);
        }
        CP_COMMIT();
    };

    issueKV(0, 0);
    CP_WAIT0();
    __syncthreads();

    unsigned qf[8][4];
#pragma unroll
    for (int s = 0; s < 8; s++) {
        int r0 = w * 16 + gid;
        qf[s][0] = ftou(Qs[r0 * 64 + ((s * 8 + tig) ^ (4 * gid))]);
        qf[s][1] = ftou(Qs[(r0 + 8) * 64 + ((s * 8 + tig) ^ (4 * gid))]);
        qf[s][2] = ftou(Qs[r0 * 64 + ((s * 8 + tig + 4) ^ (4 * gid))]);
        qf[s][3] = ftou(Qs[(r0 + 8) * 64 + ((s * 8 + tig + 4) ^ (4 * gid))]);
    }

    float oacc[8][4];
#pragma unroll
    for (int n = 0; n < 8; n++)
#pragma unroll
        for (int r = 0; r < 4; r++) oacc[n][r] = 0.f;
    float ls0 = 0.f, ls1 = 0.f;   // lane-partial row sums

    const float qg0f = (float)(qt * 128 + w * 16 + gid);
    const float qg1f = qg0f + 8.f;
    float* Pw = Psb + w * 1056;

    for (int kt = 0; kt < 16; kt++) {
        CP_WAIT0();
        __syncthreads();
        if (kt < 15) issueKV(kt + 1, (kt + 1) & 1);
        const float* Kc = Ksb + (kt & 1) * 4096;
        const float* Vc = Vsb + (kt & 1) * 4096;

        // S = Q @ K^T
        float sacc[8][4];
#pragma unroll
        for (int n = 0; n < 8; n++)
#pragma unroll
            for (int r = 0; r < 4; r++) sacc[n][r] = 0.f;
#pragma unroll
        for (int s = 0; s < 8; s++) {
            unsigned kb[8][2];
#pragma unroll
            for (int nb = 0; nb < 8; nb++) {
                int row = nb * 8 + gid;
                kb[nb][0] = ftou(Kc[row * 64 + ((s * 8 + tig) ^ (4 * gid))]);
                kb[nb][1] = ftou(Kc[row * 64 + ((s * 8 + tig + 4) ^ (4 * gid))]);
            }
#pragma unroll
            for (int nb = 0; nb < 8; nb++)
                mma8(sacc[nb], qf[s], kb[nb]);
        }

        // exp (no max shift) + P store + partial row sums
#pragma unroll
        for (int nb = 0; nb < 8; nb++) {
            float c0 = (float)(kt * 64 + nb * 8 + 2 * tig);
            float p00 = __expf(sacc[nb][0] * scale - atd * fabsf(qg0f - c0));
            float p01 = __expf(sacc[nb][1] * scale - atd * fabsf(qg0f - c0 - 1.f));
            float p10 = __expf(sacc[nb][2] * scale - atd * fabsf(qg1f - c0));
            float p11 = __expf(sacc[nb][3] * scale - atd * fabsf(qg1f - c0 - 1.f));
            ls0 += p00 + p01; ls1 += p10 + p11;
            int base = nb * 132 + (tig >> 1) * 64 + gid * 4 + 2 * (tig & 1);
            *(float2*)&Pw[base]      = make_float2(f2tf(p00), f2tf(p01));
            *(float2*)&Pw[base + 32] = make_float2(f2tf(p10), f2tf(p11));
        }
        __syncwarp();

        // O += P @ V
#pragma unroll
        for (int s = 0; s < 8; s++) {
            unsigned pa[4];
            pa[0] = ftou(Pw[s * 132 + lane]);
            pa[1] = ftou(Pw[s * 132 + 32 + lane]);
            pa[2] = ftou(Pw[s * 132 + 64 + lane]);
            pa[3] = ftou(Pw[s * 132 + 96 + lane]);
            unsigned vb[8][2];
#pragma unroll
            for (int nb = 0; nb < 8; nb++) {
                int col = (nb * 8 + gid) ^ (8 * tig);
                vb[nb][0] = ftou(Vc[(s * 8 + tig) * 64 + col]);
                vb[nb][1] = ftou(Vc[(s * 8 + tig + 4) * 64 + col]);
            }
#pragma unroll
            for (int nb = 0; nb < 8; nb++)
                mma8(oacc[nb], pa, vb[nb]);
        }
        __syncwarp();
    }

    // Epilogue: reduce row sums across the 4 tig lanes (once)
#pragma unroll
    for (int o = 1; o <= 2; o <<= 1) {
        ls0 += __shfl_xor_sync(0xffffffffu, ls0, o);
        ls1 += __shfl_xor_sync(0xffffffffu, ls1, o);
    }
    float inv0 = 1.f / ls0, inv1 = 1.f / ls1;
    int t0 = b * S_ + qt * 128 + w * 16 + gid;
#pragma unroll
    for (int nb = 0; nb < 8; nb++) {
        int c = h * HD_ + nb * 8 + 2 * tig;
        *(float2*)&g_attn[(size_t)t0 * D_ + c] =
            make_float2(f2tf(oacc[nb][0] * inv0), f2tf(oacc[nb][1] * inv0));
        *(float2*)&g_attn[(size_t)(t0 + 8) * D_ + c] =
            make_float2(f2tf(oacc[nb][2] * inv1), f2tf(oacc[nb][3] * inv1));
    }
    if (tig == 0) {
        int si = (b * H_ + h) * S_ + qt * 128 + w * 16 + gid;
        g_linv[si] = inv0;
        g_linv[si + 8] = inv1;
    }
}

// ---------------------------------------------------------------------------
// Head-mean weights (tf32 MMA, no max shift; only linv needed).
// ---------------------------------------------------------------------------
#define WST 68
__global__ void __launch_bounds__(128) weights_kernel(
    const float* __restrict__ td_ptr, float* __restrict__ wout)
{
    extern __shared__ float sm[];
    float* Qb = sm;
    float* Kb = sm + 2 * 64 * WST;
    float* lsb = sm + 4 * 64 * WST;   // 2 x 64

    const int tid  = threadIdx.x;
    const int lane = tid & 31;
    const int wid  = tid >> 5;
    const int qt = blockIdx.x;
    const int b  = blockIdx.y;
    const int kt = blockIdx.z;
    const float atd = fabsf(*td_ptr);
    const float scale = 0.125f;
    const int gid = lane >> 2;
    const int tig = lane & 3;

    auto issue = [&](int h, int bf) {
        const float* qb = g_qkv + (size_t)(b * S_ + qt * 64) * D3_ + h * HD_;
        const float* kb = g_qkv + (size_t)(b * S_ + kt * 64) * D3_ + D_ + h * HD_;
        float* Qd = Qb + bf * 64 * WST;
        float* Kd = Kb + bf * 64 * WST;
#pragma unroll
        for (int l = 0; l < 8; l++) {
            int lin = tid + l * 128;
            int r = lin >> 4;
            int u = lin & 15;
            cpa16(su32(&Qd[r * WST + u * 4]), qb + (size_t)r * D3_ + u * 4);
            cpa16(su32(&Kd[r * WST + u * 4]), kb + (size_t)r * D3_ + u * 4);
        }
        CP_COMMIT();
    };

    issue(0, 0);
    {
        int si0 = (b * H_ + 0) * S_ + qt * 64;
        if (tid < 64) lsb[tid] = g_linv[si0 + tid];
    }

    float wsum[4][2][4];
#pragma unroll
    for (int mi = 0; mi < 4; mi++)
#pragma unroll
        for (int ni = 0; ni < 2; ni++)
#pragma unroll
            for (int r = 0; r < 4; r++) wsum[mi][ni][r] = 0.f;

    for (int h = 0; h < H_; h++) {
        const int bf = h & 1;
        CP_WAIT0();
        __syncthreads();
        if (h < 15) {
            issue(h + 1, bf ^ 1);
            int si0 = (b * H_ + h + 1) * S_ + qt * 64;
            if (tid < 64) lsb[(bf ^ 1) * 64 + tid] = g_linv[si0 + tid];
        }
        const float* Qc = Qb + bf * 64 * WST;
        const float* Kc = Kb + bf * 64 * WST;
        const float* ls = lsb + bf * 64;

        float acc[4][2][4];
#pragma unroll
        for (int mi = 0; mi < 4; mi++)
#pragma unroll
            for (int ni = 0; ni < 2; ni++)
#pragma unroll
                for (int r = 0; r < 4; r++) acc[mi][ni][r] = 0.f;

#pragma unroll
        for (int ks = 0; ks < 64; ks += 8) {
            unsigned af[4][4], bfr[2][2];
#pragma unroll
            for (int mi = 0; mi < 4; mi++) {
                int m = mi * 16 + gid;
                af[mi][0] = ftou(Qc[m * WST + ks + tig]);
                af[mi][1] = ftou(Qc[(m + 8) * WST + ks + tig]);
                af[mi][2] = ftou(Qc[m * WST + ks + 4 + tig]);
                af[mi][3] = ftou(Qc[(m + 8) * WST + ks + 4 + tig]);
            }
#pragma unroll
            for (int ni = 0; ni < 2; ni++) {
                int n = wid * 16 + ni * 8 + gid;
                bfr[ni][0] = ftou(Kc[n * WST + ks + tig]);
                bfr[ni][1] = ftou(Kc[n * WST + ks + 4 + tig]);
            }
#pragma unroll
            for (int mi = 0; mi < 4; mi++)
#pragma unroll
                for (int ni = 0; ni < 2; ni++)
                    mma8(acc[mi][ni], af[mi], bfr[ni]);
        }

#pragma unroll
        for (int mi = 0; mi < 4; mi++) {
            int r0 = mi * 16 + gid;
            int r1 = r0 + 8;
            int qg0 = qt * 64 + r0;
            int qg1 = qt * 64 + r1;
            float l0v = ls[r0], l1v = ls[r1];
#pragma unroll
            for (int ni = 0; ni < 2; ni++) {
                int c0 = kt * 64 + wid * 16 + ni * 8 + 2 * tig;
                float v;
                v = acc[mi][ni][0] * scale - atd * fabsf((float)(qg0 - c0));
                wsum[mi][ni][0] += __expf(v) * l0v;
                v = acc[mi][ni][1] * scale - atd * fabsf((float)(qg0 - c0 - 1));
                wsum[mi][ni][1] += __expf(v) * l0v;
                v = acc[mi][ni][2] * scale - atd * fabsf((float)(qg1 - c0));
                wsum[mi][ni][2] += __expf(v) * l1v;
                v = acc[mi][ni][3] * scale - atd * fabsf((float)(qg1 - c0 - 1));
                wsum[mi][ni][3] += __expf(v) * l1v;
            }
        }
    }

    const float inv_h = 1.0f / (float)H_;
#pragma unroll
    for (int mi = 0; mi < 4; mi++) {
        int r0 = qt * 64 + mi * 16 + gid;
#pragma unroll
        for (int ni = 0; ni < 2; ni++) {
            int c = kt * 64 + wid * 16 + ni * 8 + 2 * tig;
            float2 o0 = make_float2(wsum[mi][ni][0] * inv_h, wsum[mi][ni][1] * inv_h);
            float2 o1 = make_float2(wsum[mi][ni][2] * inv_h, wsum[mi][ni][3] * inv_h);
            *(float2*)(wout + (size_t)(b * S_ + r0) * S_ + c) = o0;
            *(float2*)(wout + (size_t)(b * S_ + r0 + 8) * S_ + c) = o1;
        }
    }
}

// ---------------------------------------------------------------------------
// Residual + LayerNorm
// ---------------------------------------------------------------------------
__global__ void __launch_bounds__(256) ln_kernel(
    const float* __restrict__ x, const float* __restrict__ lnw,
    const float* __restrict__ lnb, float* __restrict__ out)
{
    const int row = blockIdx.x;
    const int tid = threadIdx.x;
    const float* xr = x + (size_t)row * D_;
    const float* ar = g_attnout + (size_t)row * D_;

    float4 xv = *(const float4*)(xr + tid * 4);
    float4 av = *(const float4*)(ar + tid * 4);
    float y[4];
    y[0] = xv.x + av.x; y[1] = xv.y + av.y;
    y[2] = xv.z + av.z; y[3] = xv.w + av.w;

    float s  = y[0] + y[1] + y[2] + y[3];
    float sq = y[0]*y[0] + y[1]*y[1] + y[2]*y[2] + y[3]*y[3];
#pragma unroll
    for (int o = 16; o >= 1; o >>= 1) {
        s  += __shfl_xor_sync(0xffffffffu, s,  o);
        sq += __shfl_xor_sync(0xffffffffu, sq, o);
    }
    __shared__ float red[16];
    const int wid = tid >> 5;
    if ((tid & 31) == 0) { red[wid] = s; red[8 + wid] = sq; }
    __syncthreads();
    float st = 0.f, sqt = 0.f;
#pragma unroll
    for (int w = 0; w < 8; w++) { st += red[w]; sqt += red[8 + w]; }
    float mu = st * (1.0f / D_);
    float var = sqt * (1.0f / D_) - mu * mu;
    float rstd = rsqrtf(var + 1e-5f);

    float4 wv = *(const float4*)(lnw + tid * 4);
    float4 bv = *(const float4*)(lnb + tid * 4);
    float4 o4;
    o4.x = (y[0] - mu) * rstd * wv.x + bv.x;
    o4.y = (y[1] - mu) * rstd * wv.y + bv.y;
    o4.z = (y[2] - mu) * rstd * wv.z + bv.z;
    o4.w = (y[3] - mu) * rstd * wv.w + bv.w;
    *(float4*)(out + (size_t)row * D_ + tid * 4) = o4;
}

// ---------------------------------------------------------------------------
extern "C" void kernel_launch(void* const* d_in, const int* in_sizes, int n_in,
                              void* d_out, int out_size)
{
    (void)in_sizes; (void)n_in; (void)out_size;
    const float* x     = (const float*)d_in[0];
    const float* td    = (const float*)d_in[1];
    const float* in_w  = (const float*)d_in[2];
    const float* in_b  = (const float*)d_in[3];
    const float* out_w = (const float*)d_in[4];
    const float* out_b = (const float*)d_in[5];
    const float* lnw   = (const float*)d_in[6];
    const float* lnb   = (const float*)d_in[7];
    float* out  = (float*)d_out;
    float* wout = out + (size_t)T_ * D_;

    float *qkv_p, *attn_p, *attnout_p, *xr_p, *wi_p, *wo_p;
    cudaGetSymbolAddress((void**)&qkv_p, g_qkv);
    cudaGetSymbolAddress((void**)&attn_p, g_attn);
    cudaGetSymbolAddress((void**)&attnout_p, g_attnout);
    cudaGetSymbolAddress((void**)&xr_p, g_xr);
    cudaGetSymbolAddress((void**)&wi_p, g_wi);
    cudaGetSymbolAddress((void**)&wo_p, g_wo);

    const int gsmem = 3 * 2 * 128 * GST * 4;
    const int fsmem = (8192 + 8192 + 8192 + 8 * 1056) * 4;
    const int wsmem = (4 * 64 * WST + 128) * 4;
    cudaFuncSetAttribute(gemm_tf32_kernel<true>,
                         cudaFuncAttributeMaxDynamicSharedMemorySize, gsmem);
    cudaFuncSetAttribute(gemm_tf32_kernel<false>,
                         cudaFuncAttributeMaxDynamicSharedMemorySize, gsmem);
    cudaFuncSetAttribute(flash_kernel,
                         cudaFuncAttributeMaxDynamicSharedMemorySize, fsmem);
    cudaFuncSetAttribute(weights_kernel,
                         cudaFuncAttributeMaxDynamicSharedMemorySize, wsmem);

    // 0. Pre-round GEMM inputs to tf32 (removes all in-loop cvt)
    {
        int n4;
        n4 = (T_ * D_) / 4;
        round_tf32_kernel<<<(n4 + 255) / 256, 256>>>(x, xr_p, n4);
        n4 = (D3_ * D_) / 4;
        round_tf32_kernel<<<(n4 + 255) / 256, 256>>>(in_w, wi_p, n4);
        n4 = (D_ * D_) / 4;
        round_tf32_kernel<<<(n4 + 255) / 256, 256>>>(out_w, wo_p, n4);
    }

    // 1. QKV projection (tf32-rounded output)
    gemm_tf32_kernel<true><<<dim3(3 * D_ / 128, T_ / 128), 256, gsmem>>>(
        xr_p, wi_p, in_b, qkv_p, T_, 3 * D_, D_);

    // 2. Flash attention -> g_attn (tf32-rounded), g_linv
    flash_kernel<<<dim3(B_ * H_, S_ / 128), 256, fsmem>>>(td);

    // 3. Head-mean weights -> second output
    weights_kernel<<<dim3(S_ / 64, B_, S_ / 64), 128, wsmem>>>(td, wout);

    // 4. Out projection (fp32 output)
    gemm_tf32_kernel<false><<<dim3(D_ / 128, T_ / 128), 256, gsmem>>>(
        attn_p, wo_p, out_b, attnout_p, T_, D_, D_);

    // 5. Residual + LayerNorm
    ln_kernel<<<T_, 256>>>(x, lnw, lnb, out);
}

// round 6
// speedup vs baseline: 1.4060x; 1.4060x over previous
#include <cuda_runtime.h>
#include <cuda_fp16.h>

// Problem constants
#define S_   1024
#define B_   8
#define D_   1024
#define H_   16
#define HD_  64
#define T_   (B_ * S_)
#define D3_  (3 * D_)

// Scratch
__device__ float  g_qkv[(size_t)T_ * 3 * D_];     // fp32 (fp16-rounded values)
__device__ __half g_attnh[(size_t)T_ * D_];       // fp16 attention output
__device__ float  g_attnout[(size_t)T_ * D_];
__device__ float  g_linv[B_ * H_ * S_];
__device__ __half g_xh[(size_t)T_ * D_];          // fp16 x
__device__ __half g_wih[(size_t)D3_ * D_];        // fp16 in_proj_w
__device__ __half g_woh[(size_t)D_ * D_];         // fp16 out_proj_w

__device__ __forceinline__ unsigned su32(const void* p) {
    return (unsigned)__cvta_generic_to_shared(p);
}
__device__ __forceinline__ void cpa16(unsigned dst, const void* src) {
    asm volatile("cp.async.cg.shared.global [%0], [%1], 16;" :: "r"(dst), "l"(src));
}
#define CP_COMMIT() asm volatile("cp.async.commit_group;")
#define CP_WAIT0()  asm volatile("cp.async.wait_group 0;")
#define CP_WAIT2()  asm volatile("cp.async.wait_group 2;")

__device__ __forceinline__ float f2tf(float x) {
    unsigned r;
    asm("cvt.rna.tf32.f32 %0, %1;" : "=r"(r) : "f"(x));
    return __uint_as_float(r);
}
__device__ __forceinline__ unsigned ftou(float x) { return __float_as_uint(x); }

// tf32 m16n8k8 (flash / weights kernels)
__device__ __forceinline__ void mma8(float* d, const unsigned* a, const unsigned* b) {
    asm volatile(
        "mma.sync.aligned.m16n8k8.row.col.f32.tf32.tf32.f32 "
        "{%0,%1,%2,%3},{%4,%5,%6,%7},{%8,%9},{%0,%1,%2,%3};"
        : "+f"(d[0]), "+f"(d[1]), "+f"(d[2]), "+f"(d[3])
        : "r"(a[0]), "r"(a[1]), "r"(a[2]), "r"(a[3]), "r"(b[0]), "r"(b[1]));
}
// fp16 m16n8k16 (projection GEMMs)
__device__ __forceinline__ void mma16h(float* d, const unsigned* a, const unsigned* b) {
    asm volatile(
        "mma.sync.aligned.m16n8k16.row.col.f32.f16.f16.f32 "
        "{%0,%1,%2,%3},{%4,%5,%6,%7},{%8,%9},{%0,%1,%2,%3};"
        : "+f"(d[0]), "+f"(d[1]), "+f"(d[2]), "+f"(d[3])
        : "r"(a[0]), "r"(a[1]), "r"(a[2]), "r"(a[3]), "r"(b[0]), "r"(b[1]));
}
__device__ __forceinline__ void ldm4(unsigned* r, unsigned addr) {
    asm volatile("ldmatrix.sync.aligned.m8n8.x4.shared.b16 {%0,%1,%2,%3}, [%4];"
        : "=r"(r[0]), "=r"(r[1]), "=r"(r[2]), "=r"(r[3]) : "r"(addr));
}

// ---------------------------------------------------------------------------
// fp32 -> fp16 conversion (float4 grid-stride)
// ---------------------------------------------------------------------------
__global__ void __launch_bounds__(256) to_half_kernel(
    const float* __restrict__ src, __half* __restrict__ dst, int n4)
{
    int i = blockIdx.x * blockDim.x + threadIdx.x;
    if (i < n4) {
        float4 v = ((const float4*)src)[i];
        ((__half2*)dst)[2 * i]     = __floats2half2_rn(v.x, v.y);
        ((__half2*)dst)[2 * i + 1] = __floats2half2_rn(v.z, v.w);
    }
}

// ---------------------------------------------------------------------------
// fp16 GEMM (ldmatrix + m16n8k16), cp.async 3-stage, BK=32.
// C[M,N] = A[M,K] @ B[N,K]^T + bias[N].  RH: round C to fp16 (store fp32).
// smem row stride 40 halves -> conflict-free ldmatrix.
// ---------------------------------------------------------------------------
#define SKH 40
template<bool RH>
__global__ void __launch_bounds__(256) gemm_hf_kernel(
    const __half* __restrict__ A, const __half* __restrict__ Bm,
    const float* __restrict__ bias, float* __restrict__ C,
    int M, int N, int K)
{
    extern __shared__ __half smh[];
    __half* Ash = smh;                      // 3 x 128*SKH
    __half* Bsh = smh + 3 * 128 * SKH;

    const int tid  = threadIdx.x;
    const int lane = tid & 31;
    const int wid  = tid >> 5;
    const int wm   = wid & 1;
    const int wn   = wid >> 1;
    const int m0 = blockIdx.y * 128;
    const int n0 = blockIdx.x * 128;
    const int lr = tid >> 1;
    const int lc = (tid & 1) * 16;
    const __half* Ap = A  + (size_t)(m0 + lr) * K + lc;
    const __half* Bp = Bm + (size_t)(n0 + lr) * K + lc;
    const int gid = lane >> 2;
    const int tig = lane & 3;

    // ldmatrix lane offsets
    const int aRow = lane & 15;
    const int aCol = (lane >> 4) << 3;
    const int bRow = ((lane >> 4) << 3) + (lane & 7);
    const int bCol = ((lane >> 3) & 1) << 3;

    auto issue = [&](int st, int k0) {
        __half* Ad = Ash + st * (128 * SKH) + lr * SKH + lc;
        __half* Bd = Bsh + st * (128 * SKH) + lr * SKH + lc;
        cpa16(su32(Ad),     Ap + k0);
        cpa16(su32(Ad + 8), Ap + k0 + 8);
        cpa16(su32(Bd),     Bp + k0);
        cpa16(su32(Bd + 8), Bp + k0 + 8);
        CP_COMMIT();
    };

    float acc[4][4][4];
#pragma unroll
    for (int i = 0; i < 4; i++)
#pragma unroll
        for (int j = 0; j < 4; j++)
#pragma unroll
            for (int r = 0; r < 4; r++) acc[i][j][r] = 0.f;

    issue(0, 0); issue(1, 32); issue(2, 64);

    const int NIT = K / 32;
    int st = 0;
    for (int i = 0; i < NIT; i++) {
        CP_WAIT2();
        __syncthreads();
        const __half* Ac = Ash + st * (128 * SKH);
        const __half* Bc = Bsh + st * (128 * SKH);
#pragma unroll
        for (int ks = 0; ks < 32; ks += 16) {
            unsigned af[4][4], bf[2][4];
#pragma unroll
            for (int mi = 0; mi < 4; mi++)
                ldm4(af[mi], su32(Ac + (wm * 64 + mi * 16 + aRow) * SKH + ks + aCol));
#pragma unroll
            for (int nj = 0; nj < 2; nj++)
                ldm4(bf[nj], su32(Bc + (wn * 32 + nj * 16 + bRow) * SKH + ks + bCol));
#pragma unroll
            for (int mi = 0; mi < 4; mi++)
#pragma unroll
                for (int ni = 0; ni < 4; ni++)
                    mma16h(acc[mi][ni], af[mi], &bf[ni >> 1][(ni & 1) * 2]);
        }
        __syncthreads();
        if (i + 3 < NIT) issue(st, (i + 3) * 32);
        st = (st == 2) ? 0 : st + 1;
    }

#pragma unroll
    for (int mi = 0; mi < 4; mi++) {
        int m = m0 + wm * 64 + mi * 16 + gid;
#pragma unroll
        for (int ni = 0; ni < 4; ni++) {
            int n = n0 + wn * 32 + ni * 8 + 2 * tig;
            float bx = bias[n], by = bias[n + 1];
            float2 o0, o1;
            if (RH) {
                o0.x = __half2float(__float2half_rn(acc[mi][ni][0] + bx));
                o0.y = __half2float(__float2half_rn(acc[mi][ni][1] + by));
                o1.x = __half2float(__float2half_rn(acc[mi][ni][2] + bx));
                o1.y = __half2float(__float2half_rn(acc[mi][ni][3] + by));
            } else {
                o0 = make_float2(acc[mi][ni][0] + bx, acc[mi][ni][1] + by);
                o1 = make_float2(acc[mi][ni][2] + bx, acc[mi][ni][3] + by);
            }
            *(float2*)(C + (size_t)m * N + n) = o0;
            *(float2*)(C + (size_t)(m + 8) * N + n) = o1;
        }
    }
}

// ---------------------------------------------------------------------------
// Flash attention, tf32 tensor-core, no online max. Writes fp16 g_attnh.
// ---------------------------------------------------------------------------
__global__ void __launch_bounds__(256) flash_kernel(const float* __restrict__ td_ptr)
{
    extern __shared__ float sm[];
    float* Qs  = sm;            // 8192
    float* Ksb = sm + 8192;     // 2 x 4096
    float* Vsb = sm + 16384;    // 2 x 4096
    float* Psb = sm + 24576;    // 8 x 1056

    const int tid  = threadIdx.x;
    const int lane = tid & 31;
    const int w    = tid >> 5;
    const int gid  = lane >> 2;
    const int tig  = lane & 3;
    const int bh = blockIdx.x;
    const int qt = blockIdx.y;
    const int b  = bh >> 4;
    const int h  = bh & 15;
    const float atd = fabsf(*td_ptr);
    const float scale = 0.125f;

    {
        const float* qb = g_qkv + (size_t)(b * S_ + qt * 128) * D3_ + h * HD_;
#pragma unroll
        for (int l = 0; l < 8; l++) {
            int lin = tid + l * 256;
            int r = lin >> 4;
            int u = lin & 15;
            cpa16(su32(&Qs[r * 64 + ((4 * u) ^ (4 * (r & 7)))]),
                  qb + (size_t)r * D3_ + u * 4);
        }
    }
    auto issueKV = [&](int kt, int bf) {
        const float* kb = g_qkv + (size_t)(b * S_ + kt * 64) * D3_ + D_ + h * HD_;
        const float* vb = kb + D_;
        float* Kd = Ksb + bf * 4096;
        float* Vd = Vsb + bf * 4096;
#pragma unroll
        for (int l = 0; l < 4; l++) {
            int lin = tid + l * 256;
            int r = lin >> 4;
            int u = lin & 15;
            cpa16(su32(&Kd[r * 64 + ((4 * u) ^ (4 * (r & 7)))]), kb + (size_t)r * D3_ + u * 4);
            cpa16(su32(&Vd[r * 64 + ((4 * u) ^ (8 * (r & 3)))]), vb + (size_t)r * D3_ + u * 4);
        }
        CP_COMMIT();
    };

    issueKV(0, 0);
    CP_WAIT0();
    __syncthreads();

    unsigned qf[8][4];
#pragma unroll
    for (int s = 0; s < 8; s++) {
        int r0 = w * 16 + gid;
        qf[s][0] = ftou(Qs[r0 * 64 + ((s * 8 + tig) ^ (4 * gid))]);
        qf[s][1] = ftou(Qs[(r0 + 8) * 64 + ((s * 8 + tig) ^ (4 * gid))]);
        qf[s][2] = ftou(Qs[r0 * 64 + ((s * 8 + tig + 4) ^ (4 * gid))]);
        qf[s][3] = ftou(Qs[(r0 + 8) * 64 + ((s * 8 + tig + 4) ^ (4 * gid))]);
    }

    float oacc[8][4];
#pragma unroll
    for (int n = 0; n < 8; n++)
#pragma unroll
        for (int r = 0; r < 4; r++) oacc[n][r] = 0.f;
    float ls0 = 0.f, ls1 = 0.f;

    const float qg0f = (float)(qt * 128 + w * 16 + gid);
    const float qg1f = qg0f + 8.f;
    float* Pw = Psb + w * 1056;

    for (int kt = 0; kt < 16; kt++) {
        CP_WAIT0();
        __syncthreads();
        if (kt < 15) issueKV(kt + 1, (kt + 1) & 1);
        const float* Kc = Ksb + (kt & 1) * 4096;
        const float* Vc = Vsb + (kt & 1) * 4096;

        float sacc[8][4];
#pragma unroll
        for (int n = 0; n < 8; n++)
#pragma unroll
            for (int r = 0; r < 4; r++) sacc[n][r] = 0.f;
#pragma unroll
        for (int s = 0; s < 8; s++) {
            unsigned kb[8][2];
#pragma unroll
            for (int nb = 0; nb < 8; nb++) {
                int row = nb * 8 + gid;
                kb[nb][0] = ftou(Kc[row * 64 + ((s * 8 + tig) ^ (4 * gid))]);
                kb[nb][1] = ftou(Kc[row * 64 + ((s * 8 + tig + 4) ^ (4 * gid))]);
            }
#pragma unroll
            for (int nb = 0; nb < 8; nb++)
                mma8(sacc[nb], qf[s], kb[nb]);
        }

#pragma unroll
        for (int nb = 0; nb < 8; nb++) {
            float c0 = (float)(kt * 64 + nb * 8 + 2 * tig);
            float p00 = __expf(sacc[nb][0] * scale - atd * fabsf(qg0f - c0));
            float p01 = __expf(sacc[nb][1] * scale - atd * fabsf(qg0f - c0 - 1.f));
            float p10 = __expf(sacc[nb][2] * scale - atd * fabsf(qg1f - c0));
            float p11 = __expf(sacc[nb][3] * scale - atd * fabsf(qg1f - c0 - 1.f));
            ls0 += p00 + p01; ls1 += p10 + p11;
            int base = nb * 132 + (tig >> 1) * 64 + gid * 4 + 2 * (tig & 1);
            *(float2*)&Pw[base]      = make_float2(f2tf(p00), f2tf(p01));
            *(float2*)&Pw[base + 32] = make_float2(f2tf(p10), f2tf(p11));
        }
        __syncwarp();

#pragma unroll
        for (int s = 0; s < 8; s++) {
            unsigned pa[4];
            pa[0] = ftou(Pw[s * 132 + lane]);
            pa[1] = ftou(Pw[s * 132 + 32 + lane]);
            pa[2] = ftou(Pw[s * 132 + 64 + lane]);
            pa[3] = ftou(Pw[s * 132 + 96 + lane]);
            unsigned vb[8][2];
#pragma unroll
            for (int nb = 0; nb < 8; nb++) {
                int col = (nb * 8 + gid) ^ (8 * tig);
                vb[nb][0] = ftou(Vc[(s * 8 + tig) * 64 + col]);
                vb[nb][1] = ftou(Vc[(s * 8 + tig + 4) * 64 + col]);
            }
#pragma unroll
            for (int nb = 0; nb < 8; nb++)
                mma8(oacc[nb], pa, vb[nb]);
        }
        __syncwarp();
    }

#pragma unroll
    for (int o = 1; o <= 2; o <<= 1) {
        ls0 += __shfl_xor_sync(0xffffffffu, ls0, o);
        ls1 += __shfl_xor_sync(0xffffffffu, ls1, o);
    }
    float inv0 = 1.f / ls0, inv1 = 1.f / ls1;
    int t0 = b * S_ + qt * 128 + w * 16 + gid;
#pragma unroll
    for (int nb = 0; nb < 8; nb++) {
        int c = h * HD_ + nb * 8 + 2 * tig;
        *(__half2*)&g_attnh[(size_t)t0 * D_ + c] =
            __floats2half2_rn(oacc[nb][0] * inv0, oacc[nb][1] * inv0);
        *(__half2*)&g_attnh[(size_t)(t0 + 8) * D_ + c] =
            __floats2half2_rn(oacc[nb][2] * inv1, oacc[nb][3] * inv1);
    }
    if (tig == 0) {
        int si = (b * H_ + h) * S_ + qt * 128 + w * 16 + gid;
        g_linv[si] = inv0;
        g_linv[si + 8] = inv1;
    }
}

// ---------------------------------------------------------------------------
// Head-mean weights (tf32 MMA, no max shift).
// ---------------------------------------------------------------------------
#define WST 68
__global__ void __launch_bounds__(128) weights_kernel(
    const float* __restrict__ td_ptr, float* __restrict__ wout)
{
    extern __shared__ float sm[];
    float* Qb = sm;
    float* Kb = sm + 2 * 64 * WST;
    float* lsb = sm + 4 * 64 * WST;

    const int tid  = threadIdx.x;
    const int lane = tid & 31;
    const int wid  = tid >> 5;
    const int qt = blockIdx.x;
    const int b  = blockIdx.y;
    const int kt = blockIdx.z;
    const float atd = fabsf(*td_ptr);
    const float scale = 0.125f;
    const int gid = lane >> 2;
    const int tig = lane & 3;

    auto issue = [&](int h, int bf) {
        const float* qb = g_qkv + (size_t)(b * S_ + qt * 64) * D3_ + h * HD_;
        const float* kb = g_qkv + (size_t)(b * S_ + kt * 64) * D3_ + D_ + h * HD_;
        float* Qd = Qb + bf * 64 * WST;
        float* Kd = Kb + bf * 64 * WST;
#pragma unroll
        for (int l = 0; l < 8; l++) {
            int lin = tid + l * 128;
            int r = lin >> 4;
            int u = lin & 15;
            cpa16(su32(&Qd[r * WST + u * 4]), qb + (size_t)r * D3_ + u * 4);
            cpa16(su32(&Kd[r * WST + u * 4]), kb + (size_t)r * D3_ + u * 4);
        }
        CP_COMMIT();
    };

    issue(0, 0);
    {
        int si0 = (b * H_ + 0) * S_ + qt * 64;
        if (tid < 64) lsb[tid] = g_linv[si0 + tid];
    }

    float wsum[4][2][4];
#pragma unroll
    for (int mi = 0; mi < 4; mi++)
#pragma unroll
        for (int ni = 0; ni < 2; ni++)
#pragma unroll
            for (int r = 0; r < 4; r++) wsum[mi][ni][r] = 0.f;

    for (int h = 0; h < H_; h++) {
        const int bf = h & 1;
        CP_WAIT0();
        __syncthreads();
        if (h < 15) {
            issue(h + 1, bf ^ 1);
            int si0 = (b * H_ + h + 1) * S_ + qt * 64;
            if (tid < 64) lsb[(bf ^ 1) * 64 + tid] = g_linv[si0 + tid];
        }
        const float* Qc = Qb + bf * 64 * WST;
        const float* Kc = Kb + bf * 64 * WST;
        const float* ls = lsb + bf * 64;

        float acc[4][2][4];
#pragma unroll
        for (int mi = 0; mi < 4; mi++)
#pragma unroll
            for (int ni = 0; ni < 2; ni++)
#pragma unroll
                for (int r = 0; r < 4; r++) acc[mi][ni][r] = 0.f;

#pragma unroll
        for (int ks = 0; ks < 64; ks += 8) {
            unsigned af[4][4], bfr[2][2];
#pragma unroll
            for (int mi = 0; mi < 4; mi++) {
                int m = mi * 16 + gid;
                af[mi][0] = ftou(Qc[m * WST + ks + tig]);
                af[mi][1] = ftou(Qc[(m + 8) * WST + ks + tig]);
                af[mi][2] = ftou(Qc[m * WST + ks + 4 + tig]);
                af[mi][3] = ftou(Qc[(m + 8) * WST + ks + 4 + tig]);
            }
#pragma unroll
            for (int ni = 0; ni < 2; ni++) {
                int n = wid * 16 + ni * 8 + gid;
                bfr[ni][0] = ftou(Kc[n * WST + ks + tig]);
                bfr[ni][1] = ftou(Kc[n * WST + ks + 4 + tig]);
            }
#pragma unroll
            for (int mi = 0; mi < 4; mi++)
#pragma unroll
                for (int ni = 0; ni < 2; ni++)
                    mma8(acc[mi][ni], af[mi], bfr[ni]);
        }

#pragma unroll
        for (int mi = 0; mi < 4; mi++) {
            int r0 = mi * 16 + gid;
            int r1 = r0 + 8;
            int qg0 = qt * 64 + r0;
            int qg1 = qt * 64 + r1;
            float l0v = ls[r0], l1v = ls[r1];
#pragma unroll
            for (int ni = 0; ni < 2; ni++) {
                int c0 = kt * 64 + wid * 16 + ni * 8 + 2 * tig;
                float v;
                v = acc[mi][ni][0] * scale - atd * fabsf((float)(qg0 - c0));
                wsum[mi][ni][0] += __expf(v) * l0v;
                v = acc[mi][ni][1] * scale - atd * fabsf((float)(qg0 - c0 - 1));
                wsum[mi][ni][1] += __expf(v) * l0v;
                v = acc[mi][ni][2] * scale - atd * fabsf((float)(qg1 - c0));
                wsum[mi][ni][2] += __expf(v) * l1v;
                v = acc[mi][ni][3] * scale - atd * fabsf((float)(qg1 - c0 - 1));
                wsum[mi][ni][3] += __expf(v) * l1v;
            }
        }
    }

    const float inv_h = 1.0f / (float)H_;
#pragma unroll
    for (int mi = 0; mi < 4; mi++) {
        int r0 = qt * 64 + mi * 16 + gid;
#pragma unroll
        for (int ni = 0; ni < 2; ni++) {
            int c = kt * 64 + wid * 16 + ni * 8 + 2 * tig;
            float2 o0 = make_float2(wsum[mi][ni][0] * inv_h, wsum[mi][ni][1] * inv_h);
            float2 o1 = make_float2(wsum[mi][ni][2] * inv_h, wsum[mi][ni][3] * inv_h);
            *(float2*)(wout + (size_t)(b * S_ + r0) * S_ + c) = o0;
            *(float2*)(wout + (size_t)(b * S_ + r0 + 8) * S_ + c) = o1;
        }
    }
}

// ---------------------------------------------------------------------------
// Residual + LayerNorm
// ---------------------------------------------------------------------------
__global__ void __launch_bounds__(256) ln_kernel(
    const float* __restrict__ x, const float* __restrict__ lnw,
    const float* __restrict__ lnb, float* __restrict__ out)
{
    const int row = blockIdx.x;
    const int tid = threadIdx.x;
    const float* xr = x + (size_t)row * D_;
    const float* ar = g_attnout + (size_t)row * D_;

    float4 xv = *(const float4*)(xr + tid * 4);
    float4 av = *(const float4*)(ar + tid * 4);
    float y[4];
    y[0] = xv.x + av.x; y[1] = xv.y + av.y;
    y[2] = xv.z + av.z; y[3] = xv.w + av.w;

    float s  = y[0] + y[1] + y[2] + y[3];
    float sq = y[0]*y[0] + y[1]*y[1] + y[2]*y[2] + y[3]*y[3];
#pragma unroll
    for (int o = 16; o >= 1; o >>= 1) {
        s  += __shfl_xor_sync(0xffffffffu, s,  o);
        sq += __shfl_xor_sync(0xffffffffu, sq, o);
    }
    __shared__ float red[16];
    const int wid = tid >> 5;
    if ((tid & 31) == 0) { red[wid] = s; red[8 + wid] = sq; }
    __syncthreads();
    float st = 0.f, sqt = 0.f;
#pragma unroll
    for (int w = 0; w < 8; w++) { st += red[w]; sqt += red[8 + w]; }
    float mu = st * (1.0f / D_);
    float var = sqt * (1.0f / D_) - mu * mu;
    float rstd = rsqrtf(var + 1e-5f);

    float4 wv = *(const float4*)(lnw + tid * 4);
    float4 bv = *(const float4*)(lnb + tid * 4);
    float4 o4;
    o4.x = (y[0] - mu) * rstd * wv.x + bv.x;
    o4.y = (y[1] - mu) * rstd * wv.y + bv.y;
    o4.z = (y[2] - mu) * rstd * wv.z + bv.z;
    o4.w = (y[3] - mu) * rstd * wv.w + bv.w;
    *(float4*)(out + (size_t)row * D_ + tid * 4) = o4;
}

// ---------------------------------------------------------------------------
extern "C" void kernel_launch(void* const* d_in, const int* in_sizes, int n_in,
                              void* d_out, int out_size)
{
    (void)in_sizes; (void)n_in; (void)out_size;
    const float* x     = (const float*)d_in[0];
    const float* td    = (const float*)d_in[1];
    const float* in_w  = (const float*)d_in[2];
    const float* in_b  = (const float*)d_in[3];
    const float* out_w = (const float*)d_in[4];
    const float* out_b = (const float*)d_in[5];
    const float* lnw   = (const float*)d_in[6];
    const float* lnb   = (const float*)d_in[7];
    float* out  = (float*)d_out;
    float* wout = out + (size_t)T_ * D_;

    float *qkv_p, *attnout_p;
    __half *xh_p, *wih_p, *woh_p, *attnh_p;
    cudaGetSymbolAddress((void**)&qkv_p, g_qkv);
    cudaGetSymbolAddress((void**)&attnout_p, g_attnout);
    cudaGetSymbolAddress((void**)&xh_p, g_xh);
    cudaGetSymbolAddress((void**)&wih_p, g_wih);
    cudaGetSymbolAddress((void**)&woh_p, g_woh);
    cudaGetSymbolAddress((void**)&attnh_p, g_attnh);

    const int gsmem = 3 * 2 * 128 * SKH * 2;               // 61440 B
    const int fsmem = (8192 + 8192 + 8192 + 8 * 1056) * 4;
    const int wsmem = (4 * 64 * WST + 128) * 4;
    cudaFuncSetAttribute(gemm_hf_kernel<true>,
                         cudaFuncAttributeMaxDynamicSharedMemorySize, gsmem);
    cudaFuncSetAttribute(gemm_hf_kernel<false>,
                         cudaFuncAttributeMaxDynamicSharedMemorySize, gsmem);
    cudaFuncSetAttribute(flash_kernel,
                         cudaFuncAttributeMaxDynamicSharedMemorySize, fsmem);
    cudaFuncSetAttribute(weights_kernel,
                         cudaFuncAttributeMaxDynamicSharedMemorySize, wsmem);

    // 0. Convert GEMM inputs to fp16
    {
        int n4;
        n4 = (T_ * D_) / 4;
        to_half_kernel<<<(n4 + 255) / 256, 256>>>(x, xh_p, n4);
        n4 = (D3_ * D_) / 4;
        to_half_kernel<<<(n4 + 255) / 256, 256>>>(in_w, wih_p, n4);
        n4 = (D_ * D_) / 4;
        to_half_kernel<<<(n4 + 255) / 256, 256>>>(out_w, woh_p, n4);
    }

    // 1. QKV projection (fp16 MMA; output stored fp32 = fp16-rounded, tf32-valid)
    gemm_hf_kernel<true><<<dim3(3 * D_ / 128, T_ / 128), 256, gsmem>>>(
        xh_p, wih_p, in_b, qkv_p, T_, 3 * D_, D_);

    // 2. Flash attention -> g_attnh (fp16), g_linv
    flash_kernel<<<dim3(B_ * H_, S_ / 128), 256, fsmem>>>(td);

    // 3. Head-mean weights -> second output
    weights_kernel<<<dim3(S_ / 64, B_, S_ / 64), 128, wsmem>>>(td, wout);

    // 4. Out projection (fp16 MMA, fp32 output)
    gemm_hf_kernel<false><<<dim3(D_ / 128, T_ / 128), 256, gsmem>>>(
        attnh_p, woh_p, out_b, attnout_p, T_, D_, D_);

    // 5. Residual + LayerNorm
    ln_kernel<<<T_, 256>>>(x, lnw, lnb, out);
}

// round 8
// speedup vs baseline: 1.9554x; 1.3908x over previous
#include <cuda_runtime.h>
#include <cuda_fp16.h>

// Problem constants
#define S_   1024
#define B_   8
#define D_   1024
#define H_   16
#define HD_  64
#define T_   (B_ * S_)
#define D3_  (3 * D_)

// Scratch
__device__ __half g_qkvh[(size_t)T_ * 3 * D_];    // fp16 q|k|v
__device__ __half g_attnh[(size_t)T_ * D_];       // fp16 attention output
__device__ float  g_attnout[(size_t)T_ * D_];
__device__ float  g_linv[B_ * H_ * S_];
__device__ __half g_xh[(size_t)T_ * D_];
__device__ __half g_wih[(size_t)D3_ * D_];
__device__ __half g_woh[(size_t)D_ * D_];

__device__ __forceinline__ unsigned su32(const void* p) {
    return (unsigned)__cvta_generic_to_shared(p);
}
__device__ __forceinline__ void cpa16(unsigned dst, const void* src) {
    asm volatile("cp.async.cg.shared.global [%0], [%1], 16;" :: "r"(dst), "l"(src));
}
#define CP_COMMIT() asm volatile("cp.async.commit_group;")
#define CP_WAIT0()  asm volatile("cp.async.wait_group 0;")
#define CP_WAIT2()  asm volatile("cp.async.wait_group 2;")

__device__ __forceinline__ unsigned pkh2(float a, float b) {
    __half2 h = __floats2half2_rn(a, b);
    return *(unsigned*)&h;
}

// fp16 m16n8k16
__device__ __forceinline__ void mma16h(float* d, const unsigned* a, const unsigned* b) {
    asm volatile(
        "mma.sync.aligned.m16n8k16.row.col.f32.f16.f16.f32 "
        "{%0,%1,%2,%3},{%4,%5,%6,%7},{%8,%9},{%0,%1,%2,%3};"
        : "+f"(d[0]), "+f"(d[1]), "+f"(d[2]), "+f"(d[3])
        : "r"(a[0]), "r"(a[1]), "r"(a[2]), "r"(a[3]), "r"(b[0]), "r"(b[1]));
}
__device__ __forceinline__ void ldm4(unsigned* r, unsigned addr) {
    asm volatile("ldmatrix.sync.aligned.m8n8.x4.shared.b16 {%0,%1,%2,%3}, [%4];"
        : "=r"(r[0]), "=r"(r[1]), "=r"(r[2]), "=r"(r[3]) : "r"(addr));
}
__device__ __forceinline__ void ldm4t(unsigned* r, unsigned addr) {
    asm volatile("ldmatrix.sync.aligned.m8n8.x4.trans.shared.b16 {%0,%1,%2,%3}, [%4];"
        : "=r"(r[0]), "=r"(r[1]), "=r"(r[2]), "=r"(r[3]) : "r"(addr));
}

// ---------------------------------------------------------------------------
// fp32 -> fp16 conversion
// ---------------------------------------------------------------------------
__global__ void __launch_bounds__(256) to_half_kernel(
    const float* __restrict__ src, __half* __restrict__ dst, int n4)
{
    int i = blockIdx.x * blockDim.x + threadIdx.x;
    if (i < n4) {
        float4 v = ((const float4*)src)[i];
        ((__half2*)dst)[2 * i]     = __floats2half2_rn(v.x, v.y);
        ((__half2*)dst)[2 * i + 1] = __floats2half2_rn(v.z, v.w);
    }
}

// ---------------------------------------------------------------------------
// fp16 GEMM (ldmatrix + m16n8k16), cp.async 3-stage, BK=32.
// C[M,N] = A[M,K] @ B[N,K]^T + bias[N].  HALF_OUT: C is __half*, else float*.
// Rows hold 32 halves, stride SKH=40 (conflict-free).
// ---------------------------------------------------------------------------
#define SKH 40
template<bool HALF_OUT>
__global__ void __launch_bounds__(256) gemm_hf_kernel(
    const __half* __restrict__ A, const __half* __restrict__ Bm,
    const float* __restrict__ bias, void* __restrict__ Cv,
    int M, int N, int K)
{
    extern __shared__ __half smh[];
    __half* Ash = smh;
    __half* Bsh = smh + 3 * 128 * SKH;

    const int tid  = threadIdx.x;
    const int lane = tid & 31;
    const int wid  = tid >> 5;
    const int wm   = wid & 1;
    const int wn   = wid >> 1;
    const int m0 = blockIdx.y * 128;
    const int n0 = blockIdx.x * 128;
    const int lr = tid >> 1;
    const int lc = (tid & 1) * 16;
    const __half* Ap = A  + (size_t)(m0 + lr) * K + lc;
    const __half* Bp = Bm + (size_t)(n0 + lr) * K + lc;
    const int gid = lane >> 2;
    const int tig = lane & 3;

    const int aRow = lane & 15;
    const int aCol = (lane >> 4) << 3;
    const int bRow = ((lane >> 4) << 3) + (lane & 7);
    const int bCol = ((lane >> 3) & 1) << 3;

    auto issue = [&](int st, int k0) {
        __half* Ad = Ash + st * (128 * SKH) + lr * SKH + lc;
        __half* Bd = Bsh + st * (128 * SKH) + lr * SKH + lc;
        cpa16(su32(Ad),     Ap + k0);
        cpa16(su32(Ad + 8), Ap + k0 + 8);
        cpa16(su32(Bd),     Bp + k0);
        cpa16(su32(Bd + 8), Bp + k0 + 8);
        CP_COMMIT();
    };

    float acc[4][4][4];
#pragma unroll
    for (int i = 0; i < 4; i++)
#pragma unroll
        for (int j = 0; j < 4; j++)
#pragma unroll
            for (int r = 0; r < 4; r++) acc[i][j][r] = 0.f;

    issue(0, 0); issue(1, 32); issue(2, 64);

    const int NIT = K / 32;
    int st = 0;
    for (int i = 0; i < NIT; i++) {
        CP_WAIT2();
        __syncthreads();
        const __half* Ac = Ash + st * (128 * SKH);
        const __half* Bc = Bsh + st * (128 * SKH);
#pragma unroll
        for (int ks = 0; ks < 32; ks += 16) {
            unsigned af[4][4], bf[2][4];
#pragma unroll
            for (int mi = 0; mi < 4; mi++)
                ldm4(af[mi], su32(Ac + (wm * 64 + mi * 16 + aRow) * SKH + ks + aCol));
#pragma unroll
            for (int nj = 0; nj < 2; nj++)
                ldm4(bf[nj], su32(Bc + (wn * 32 + nj * 16 + bRow) * SKH + ks + bCol));
#pragma unroll
            for (int mi = 0; mi < 4; mi++)
#pragma unroll
                for (int ni = 0; ni < 4; ni++)
                    mma16h(acc[mi][ni], af[mi], &bf[ni >> 1][(ni & 1) * 2]);
        }
        __syncthreads();
        if (i + 3 < NIT) issue(st, (i + 3) * 32);
        st = (st == 2) ? 0 : st + 1;
    }

#pragma unroll
    for (int mi = 0; mi < 4; mi++) {
        int m = m0 + wm * 64 + mi * 16 + gid;
#pragma unroll
        for (int ni = 0; ni < 4; ni++) {
            int n = n0 + wn * 32 + ni * 8 + 2 * tig;
            float bx = bias[n], by = bias[n + 1];
            if (HALF_OUT) {
                __half* C = (__half*)Cv;
                *(__half2*)(C + (size_t)m * N + n) =
                    __floats2half2_rn(acc[mi][ni][0] + bx, acc[mi][ni][1] + by);
                *(__half2*)(C + (size_t)(m + 8) * N + n) =
                    __floats2half2_rn(acc[mi][ni][2] + bx, acc[mi][ni][3] + by);
            } else {
                float* C = (float*)Cv;
                *(float2*)(C + (size_t)m * N + n) =
                    make_float2(acc[mi][ni][0] + bx, acc[mi][ni][1] + by);
                *(float2*)(C + (size_t)(m + 8) * N + n) =
                    make_float2(acc[mi][ni][2] + bx, acc[mi][ni][3] + by);
            }
        }
    }
}

// ---------------------------------------------------------------------------
// Flash attention, fp16 MMA. Rows hold 64 halves -> stride FST=72
// (144 B; 144 mod 128 = 16 -> 8 consecutive rows cover all 16B bank groups).
// smem halves: Q[128*72] K[2][64*72] V[2][64*72] = 27648 h = 55296 B
// ---------------------------------------------------------------------------
#define FST 72
__global__ void __launch_bounds__(256) flash_kernel(const float* __restrict__ td_ptr)
{
    extern __shared__ __half smh[];
    __half* Qs  = smh;                  // 128*72
    __half* Ksb = smh + 128 * FST;      // 2 x 64*72
    __half* Vsb = Ksb + 2 * 64 * FST;   // 2 x 64*72

    const int tid  = threadIdx.x;
    const int lane = tid & 31;
    const int w    = tid >> 5;
    const int gid  = lane >> 2;
    const int tig  = lane & 3;
    const int bh = blockIdx.x;
    const int qt = blockIdx.y;
    const int b  = bh >> 4;
    const int h  = bh & 15;
    const float atd = fabsf(*td_ptr);
    const float scale = 0.125f;

    const int aRow = lane & 15;
    const int aCol = (lane >> 4) << 3;
    const int bRow = ((lane >> 4) << 3) + (lane & 7);
    const int bCol = ((lane >> 3) & 1) << 3;

    // Q tile: 128 rows x 64 halves = 1024 16B chunks
    {
        const __half* qb = g_qkvh + (size_t)(b * S_ + qt * 128) * D3_ + h * HD_;
#pragma unroll
        for (int l = 0; l < 4; l++) {
            int lin = tid + l * 256;
            int r = lin >> 3;
            int u = lin & 7;
            cpa16(su32(Qs + r * FST + u * 8), qb + (size_t)r * D3_ + u * 8);
        }
    }
    auto issueKV = [&](int kt, int bf) {
        const __half* kb = g_qkvh + (size_t)(b * S_ + kt * 64) * D3_ + D_ + h * HD_;
        const __half* vb = kb + D_;
        __half* Kd = Ksb + bf * 64 * FST;
        __half* Vd = Vsb + bf * 64 * FST;
#pragma unroll
        for (int l = 0; l < 4; l++) {
            int lin = tid + l * 256;       // 0..1023
            int r = lin >> 3;              // 0..127
            int u = lin & 7;
            if (r < 64)
                cpa16(su32(Kd + r * FST + u * 8), kb + (size_t)r * D3_ + u * 8);
            else
                cpa16(su32(Vd + (r - 64) * FST + u * 8), vb + (size_t)(r - 64) * D3_ + u * 8);
        }
        CP_COMMIT();
    };

    issueKV(0, 0);
    CP_WAIT0();
    __syncthreads();

    // Hoist Q fragments (4 k-blocks of 16)
    unsigned qf[4][4];
#pragma unroll
    for (int s = 0; s < 4; s++)
        ldm4(qf[s], su32(Qs + (w * 16 + aRow) * FST + s * 16 + aCol));

    float oacc[8][4];
#pragma unroll
    for (int n = 0; n < 8; n++)
#pragma unroll
        for (int r = 0; r < 4; r++) oacc[n][r] = 0.f;
    float ls0 = 0.f, ls1 = 0.f;

    const float qg0f = (float)(qt * 128 + w * 16 + gid);
    const float qg1f = qg0f + 8.f;

    for (int kt = 0; kt < 16; kt++) {
        CP_WAIT0();
        __syncthreads();
        if (kt < 15) issueKV(kt + 1, (kt + 1) & 1);
        const __half* Kc = Ksb + (kt & 1) * 64 * FST;
        const __half* Vc = Vsb + (kt & 1) * 64 * FST;

        // S = Q @ K^T  (16 x 64 per warp)
        float sacc[8][4];
#pragma unroll
        for (int n = 0; n < 8; n++)
#pragma unroll
            for (int r = 0; r < 4; r++) sacc[n][r] = 0.f;
#pragma unroll
        for (int s = 0; s < 4; s++) {
#pragma unroll
            for (int nj = 0; nj < 4; nj++) {
                unsigned kb[4];
                ldm4(kb, su32(Kc + (nj * 16 + bRow) * FST + s * 16 + bCol));
                mma16h(sacc[2 * nj],     qf[s], &kb[0]);
                mma16h(sacc[2 * nj + 1], qf[s], &kb[2]);
            }
        }

        // exp + register repack into A-fragments (no smem round-trip)
        unsigned pa[4][4];
#pragma unroll
        for (int nb = 0; nb < 8; nb++) {
            float c0 = (float)(kt * 64 + nb * 8 + 2 * tig);
            float p00 = __expf(sacc[nb][0] * scale - atd * fabsf(qg0f - c0));
            float p01 = __expf(sacc[nb][1] * scale - atd * fabsf(qg0f - c0 - 1.f));
            float p10 = __expf(sacc[nb][2] * scale - atd * fabsf(qg1f - c0));
            float p11 = __expf(sacc[nb][3] * scale - atd * fabsf(qg1f - c0 - 1.f));
            ls0 += p00 + p01; ls1 += p10 + p11;
            int j = nb >> 1;
            if ((nb & 1) == 0) {
                pa[j][0] = pkh2(p00, p01);
                pa[j][1] = pkh2(p10, p11);
            } else {
                pa[j][2] = pkh2(p00, p01);
                pa[j][3] = pkh2(p10, p11);
            }
        }

        // O += P @ V  (V via ldmatrix.trans)
#pragma unroll
        for (int j = 0; j < 4; j++) {
#pragma unroll
            for (int nd = 0; nd < 4; nd++) {
                unsigned vb[4];
                ldm4t(vb, su32(Vc + (j * 16 + aRow) * FST + nd * 16 + aCol));
                mma16h(oacc[2 * nd],     pa[j], &vb[0]);
                mma16h(oacc[2 * nd + 1], pa[j], &vb[2]);
            }
        }
    }

    // Epilogue
#pragma unroll
    for (int o = 1; o <= 2; o <<= 1) {
        ls0 += __shfl_xor_sync(0xffffffffu, ls0, o);
        ls1 += __shfl_xor_sync(0xffffffffu, ls1, o);
    }
    float inv0 = 1.f / ls0, inv1 = 1.f / ls1;
    int t0 = b * S_ + qt * 128 + w * 16 + gid;
#pragma unroll
    for (int nb = 0; nb < 8; nb++) {
        int c = h * HD_ + nb * 8 + 2 * tig;
        *(__half2*)&g_attnh[(size_t)t0 * D_ + c] =
            __floats2half2_rn(oacc[nb][0] * inv0, oacc[nb][1] * inv0);
        *(__half2*)&g_attnh[(size_t)(t0 + 8) * D_ + c] =
            __floats2half2_rn(oacc[nb][2] * inv1, oacc[nb][3] * inv1);
    }
    if (tig == 0) {
        int si = (b * H_ + h) * S_ + qt * 128 + w * 16 + gid;
        g_linv[si] = inv0;
        g_linv[si + 8] = inv1;
    }
}

// ---------------------------------------------------------------------------
// Head-mean weights, fp16 MMA. Block = (qt,b,kt), 128 thr (4 warps).
// smem: Qb[2][64*72]h Kb[2][64*72]h lsb[2*64]f  (36864 + 512 B)
// ---------------------------------------------------------------------------
__global__ void __launch_bounds__(128) weights_kernel(
    const float* __restrict__ td_ptr, float* __restrict__ wout)
{
    extern __shared__ __half smh[];
    __half* Qb = smh;                     // 2 x 64*72
    __half* Kb = smh + 2 * 64 * FST;      // 2 x 64*72
    float*  lsb = (float*)(smh + 4 * 64 * FST);

    const int tid  = threadIdx.x;
    const int lane = tid & 31;
    const int wid  = tid >> 5;
    const int qt = blockIdx.x;
    const int b  = blockIdx.y;
    const int kt = blockIdx.z;
    const float atd = fabsf(*td_ptr);
    const float scale = 0.125f;
    const int gid = lane >> 2;
    const int tig = lane & 3;

    const int aRow = lane & 15;
    const int aCol = (lane >> 4) << 3;
    const int bRow = ((lane >> 4) << 3) + (lane & 7);
    const int bCol = ((lane >> 3) & 1) << 3;

    auto issue = [&](int h, int bf) {
        const __half* qb = g_qkvh + (size_t)(b * S_ + qt * 64) * D3_ + h * HD_;
        const __half* kb = g_qkvh + (size_t)(b * S_ + kt * 64) * D3_ + D_ + h * HD_;
        __half* Qd = Qb + bf * 64 * FST;
        __half* Kd = Kb + bf * 64 * FST;
#pragma unroll
        for (int l = 0; l < 8; l++) {
            int lin = tid + l * 128;      // 0..1023
            int r = lin >> 3;             // 0..127
            int u = lin & 7;
            if (r < 64)
                cpa16(su32(Qd + r * FST + u * 8), qb + (size_t)r * D3_ + u * 8);
            else
                cpa16(su32(Kd + (r - 64) * FST + u * 8), kb + (size_t)(r - 64) * D3_ + u * 8);
        }
        CP_COMMIT();
    };

    issue(0, 0);
    {
        int si0 = (b * H_ + 0) * S_ + qt * 64;
        if (tid < 64) lsb[tid] = g_linv[si0 + tid];
    }

    float wsum[4][2][4];
#pragma unroll
    for (int mi = 0; mi < 4; mi++)
#pragma unroll
        for (int ni = 0; ni < 2; ni++)
#pragma unroll
            for (int r = 0; r < 4; r++) wsum[mi][ni][r] = 0.f;

    for (int h = 0; h < H_; h++) {
        const int bf = h & 1;
        CP_WAIT0();
        __syncthreads();
        if (h < 15) {
            issue(h + 1, bf ^ 1);
            int si0 = (b * H_ + h + 1) * S_ + qt * 64;
            if (tid < 64) lsb[(bf ^ 1) * 64 + tid] = g_linv[si0 + tid];
        }
        const __half* Qc = Qb + bf * 64 * FST;
        const __half* Kc = Kb + bf * 64 * FST;
        const float* ls = lsb + bf * 64;

        float acc[4][2][4];
#pragma unroll
        for (int mi = 0; mi < 4; mi++)
#pragma unroll
            for (int ni = 0; ni < 2; ni++)
#pragma unroll
                for (int r = 0; r < 4; r++) acc[mi][ni][r] = 0.f;

#pragma unroll
        for (int ks = 0; ks < 4; ks++) {
            unsigned bfr[4];
            ldm4(bfr, su32(Kc + (wid * 16 + bRow) * FST + ks * 16 + bCol));
#pragma unroll
            for (int mi = 0; mi < 4; mi++) {
                unsigned af[4];
                ldm4(af, su32(Qc + (mi * 16 + aRow) * FST + ks * 16 + aCol));
                mma16h(acc[mi][0], af, &bfr[0]);
                mma16h(acc[mi][1], af, &bfr[2]);
            }
        }

#pragma unroll
        for (int mi = 0; mi < 4; mi++) {
            int r0 = mi * 16 + gid;
            int r1 = r0 + 8;
            int qg0 = qt * 64 + r0;
            int qg1 = qt * 64 + r1;
            float l0v = ls[r0], l1v = ls[r1];
#pragma unroll
            for (int ni = 0; ni < 2; ni++) {
                int c0 = kt * 64 + wid * 16 + ni * 8 + 2 * tig;
                float v;
                v = acc[mi][ni][0] * scale - atd * fabsf((float)(qg0 - c0));
                wsum[mi][ni][0] += __expf(v) * l0v;
                v = acc[mi][ni][1] * scale - atd * fabsf((float)(qg0 - c0 - 1));
                wsum[mi][ni][1] += __expf(v) * l0v;
                v = acc[mi][ni][2] * scale - atd * fabsf((float)(qg1 - c0));
                wsum[mi][ni][2] += __expf(v) * l1v;
                v = acc[mi][ni][3] * scale - atd * fabsf((float)(qg1 - c0 - 1));
                wsum[mi][ni][3] += __expf(v) * l1v;
            }
        }
    }

    const float inv_h = 1.0f / (float)H_;
#pragma unroll
    for (int mi = 0; mi < 4; mi++) {
        int r0 = qt * 64 + mi * 16 + gid;
#pragma unroll
        for (int ni = 0; ni < 2; ni++) {
            int c = kt * 64 + wid * 16 + ni * 8 + 2 * tig;
            float2 o0 = make_float2(wsum[mi][ni][0] * inv_h, wsum[mi][ni][1] * inv_h);
            float2 o1 = make_float2(wsum[mi][ni][2] * inv_h, wsum[mi][ni][3] * inv_h);
            *(float2*)(wout + (size_t)(b * S_ + r0) * S_ + c) = o0;
            *(float2*)(wout + (size_t)(b * S_ + r0 + 8) * S_ + c) = o1;
        }
    }
}

// ---------------------------------------------------------------------------
// Residual + LayerNorm
// ---------------------------------------------------------------------------
__global__ void __launch_bounds__(256) ln_kernel(
    const float* __restrict__ x, const float* __restrict__ lnw,
    const float* __restrict__ lnb, float* __restrict__ out)
{
    const int row = blockIdx.x;
    const int tid = threadIdx.x;
    const float* xr = x + (size_t)row * D_;
    const float* ar = g_attnout + (size_t)row * D_;

    float4 xv = *(const float4*)(xr + tid * 4);
    float4 av = *(const float4*)(ar + tid * 4);
    float y[4];
    y[0] = xv.x + av.x; y[1] = xv.y + av.y;
    y[2] = xv.z + av.z; y[3] = xv.w + av.w;

    float s  = y[0] + y[1] + y[2] + y[3];
    float sq = y[0]*y[0] + y[1]*y[1] + y[2]*y[2] + y[3]*y[3];
#pragma unroll
    for (int o = 16; o >= 1; o >>= 1) {
        s  += __shfl_xor_sync(0xffffffffu, s,  o);
        sq += __shfl_xor_sync(0xffffffffu, sq, o);
    }
    __shared__ float red[16];
    const int wid = tid >> 5;
    if ((tid & 31) == 0) { red[wid] = s; red[8 + wid] = sq; }
    __syncthreads();
    float st = 0.f, sqt = 0.f;
#pragma unroll
    for (int w = 0; w < 8; w++) { st += red[w]; sqt += red[8 + w]; }
    float mu = st * (1.0f / D_);
    float var = sqt * (1.0f / D_) - mu * mu;
    float rstd = rsqrtf(var + 1e-5f);

    float4 wv = *(const float4*)(lnw + tid * 4);
    float4 bv = *(const float4*)(lnb + tid * 4);
    float4 o4;
    o4.x = (y[0] - mu) * rstd * wv.x + bv.x;
    o4.y = (y[1] - mu) * rstd * wv.y + bv.y;
    o4.z = (y[2] - mu) * rstd * wv.z + bv.z;
    o4.w = (y[3] - mu) * rstd * wv.w + bv.w;
    *(float4*)(out + (size_t)row * D_ + tid * 4) = o4;
}

// ---------------------------------------------------------------------------
extern "C" void kernel_launch(void* const* d_in, const int* in_sizes, int n_in,
                              void* d_out, int out_size)
{
    (void)in_sizes; (void)n_in; (void)out_size;
    const float* x     = (const float*)d_in[0];
    const float* td    = (const float*)d_in[1];
    const float* in_w  = (const float*)d_in[2];
    const float* in_b  = (const float*)d_in[3];
    const float* out_w = (const float*)d_in[4];
    const float* out_b = (const float*)d_in[5];
    const float* lnw   = (const float*)d_in[6];
    const float* lnb   = (const float*)d_in[7];
    float* out  = (float*)d_out;
    float* wout = out + (size_t)T_ * D_;

    float *attnout_p;
    __half *xh_p, *wih_p, *woh_p, *attnh_p, *qkvh_p;
    cudaGetSymbolAddress((void**)&attnout_p, g_attnout);
    cudaGetSymbolAddress((void**)&xh_p, g_xh);
    cudaGetSymbolAddress((void**)&wih_p, g_wih);
    cudaGetSymbolAddress((void**)&woh_p, g_woh);
    cudaGetSymbolAddress((void**)&attnh_p, g_attnh);
    cudaGetSymbolAddress((void**)&qkvh_p, g_qkvh);

    const int gsmem = 3 * 2 * 128 * SKH * 2;                 // 61440 B
    const int fsmem = (128 * FST + 4 * 64 * FST) * 2;        // 55296 B
    const int wsmem = 4 * 64 * FST * 2 + 2 * 64 * 4;         // 37376 B
    cudaFuncSetAttribute(gemm_hf_kernel<true>,
                         cudaFuncAttributeMaxDynamicSharedMemorySize, gsmem);
    cudaFuncSetAttribute(gemm_hf_kernel<false>,
                         cudaFuncAttributeMaxDynamicSharedMemorySize, gsmem);
    cudaFuncSetAttribute(flash_kernel,
                         cudaFuncAttributeMaxDynamicSharedMemorySize, fsmem);
    cudaFuncSetAttribute(weights_kernel,
                         cudaFuncAttributeMaxDynamicSharedMemorySize, wsmem);

    // 0. Convert GEMM inputs to fp16
    {
        int n4;
        n4 = (T_ * D_) / 4;
        to_half_kernel<<<(n4 + 255) / 256, 256>>>(x, xh_p, n4);
        n4 = (D3_ * D_) / 4;
        to_half_kernel<<<(n4 + 255) / 256, 256>>>(in_w, wih_p, n4);
        n4 = (D_ * D_) / 4;
        to_half_kernel<<<(n4 + 255) / 256, 256>>>(out_w, woh_p, n4);
    }

    // 1. QKV projection -> fp16 qkv
    gemm_hf_kernel<true><<<dim3(3 * D_ / 128, T_ / 128), 256, gsmem>>>(
        xh_p, wih_p, in_b, qkvh_p, T_, 3 * D_, D_);

    // 2. Flash attention (fp16 MMA) -> g_attnh, g_linv
    flash_kernel<<<dim3(B_ * H_, S_ / 128), 256, fsmem>>>(td);

    // 3. Head-mean weights (fp16 MMA) -> second output
    weights_kernel<<<dim3(S_ / 64, B_, S_ / 64), 128, wsmem>>>(td, wout);

    // 4. Out projection (fp32 output)
    gemm_hf_kernel<false><<<dim3(D_ / 128, T_ / 128), 256, gsmem>>>(
        attnh_p, woh_p, out_b, attnout_p, T_, D_, D_);

    // 5. Residual + LayerNorm
    ln_kernel<<<T_, 256>>>(x, lnw, lnb, out);
}

// round 10
// speedup vs baseline: 2.2925x; 1.1724x over previous
#include <cuda_runtime.h>
#include <cuda_fp16.h>
#include <cstdint>

// Problem constants
#define S_   1024
#define B_   8
#define D_   1024
#define H_   16
#define HD_  64
#define T_   (B_ * S_)
#define D3_  (3 * D_)

// Scratch
__device__ __half g_qkvh[(size_t)T_ * 3 * D_];
__device__ __half g_attnh[(size_t)T_ * D_];
__device__ float  g_attnout[(size_t)T_ * D_];
__device__ float  g_linv[B_ * H_ * S_];
__device__ __half g_xh[(size_t)T_ * D_];
__device__ __half g_wih[(size_t)D3_ * D_];
__device__ __half g_woh[(size_t)D_ * D_];

__device__ __forceinline__ unsigned su32(const void* p) {
    return (unsigned)__cvta_generic_to_shared(p);
}
__device__ __forceinline__ void cpa16(unsigned dst, const void* src) {
    asm volatile("cp.async.cg.shared.global [%0], [%1], 16;" :: "r"(dst), "l"(src));
}
#define CP_COMMIT() asm volatile("cp.async.commit_group;")
#define CP_WAIT0()  asm volatile("cp.async.wait_group 0;")
#define CP_WAIT1()  asm volatile("cp.async.wait_group 1;")
#define CP_WAIT2()  asm volatile("cp.async.wait_group 2;")

__device__ __forceinline__ unsigned pkh2(float a, float b) {
    __half2 h = __floats2half2_rn(a, b);
    return *(unsigned*)&h;
}

// fp16 m16n8k16
__device__ __forceinline__ void mma16h(float* d, const unsigned* a, const unsigned* b) {
    asm volatile(
        "mma.sync.aligned.m16n8k16.row.col.f32.f16.f16.f32 "
        "{%0,%1,%2,%3},{%4,%5,%6,%7},{%8,%9},{%0,%1,%2,%3};"
        : "+f"(d[0]), "+f"(d[1]), "+f"(d[2]), "+f"(d[3])
        : "r"(a[0]), "r"(a[1]), "r"(a[2]), "r"(a[3]), "r"(b[0]), "r"(b[1]));
}
__device__ __forceinline__ void ldm4(unsigned* r, unsigned addr) {
    asm volatile("ldmatrix.sync.aligned.m8n8.x4.shared.b16 {%0,%1,%2,%3}, [%4];"
        : "=r"(r[0]), "=r"(r[1]), "=r"(r[2]), "=r"(r[3]) : "r"(addr));
}
__device__ __forceinline__ void ldm4t(unsigned* r, unsigned addr) {
    asm volatile("ldmatrix.sync.aligned.m8n8.x4.trans.shared.b16 {%0,%1,%2,%3}, [%4];"
        : "=r"(r[0]), "=r"(r[1]), "=r"(r[2]), "=r"(r[3]) : "r"(addr));
}

// ---------------------------------------------------------------------------
// fp32 -> fp16 conversion
// ---------------------------------------------------------------------------
__global__ void __launch_bounds__(256) to_half_kernel(
    const float* __restrict__ src, __half* __restrict__ dst, int n4)
{
    int i = blockIdx.x * blockDim.x + threadIdx.x;
    if (i < n4) {
        float4 v = ((const float4*)src)[i];
        ((__half2*)dst)[2 * i]     = __floats2half2_rn(v.x, v.y);
        ((__half2*)dst)[2 * i + 1] = __floats2half2_rn(v.z, v.w);
    }
}

// ---------------------------------------------------------------------------
// fp16 GEMM: C[M,N] = A[M,K] @ B[N,K]^T + bias[N]
// 128x128 tile, BK=64 slabs (rows of 64 halves, stride FST=72 -> conflict-free),
// 3-stage cp.async, A-fragment double-buffering across k16-steps.
// ---------------------------------------------------------------------------
#define FST 72
#define GSLAB (128 * FST)            // halves per operand slab
template<bool HALF_OUT>
__global__ void __launch_bounds__(256) gemm_hf_kernel(
    const __half* __restrict__ A, const __half* __restrict__ Bm,
    const float* __restrict__ bias, void* __restrict__ Cv,
    int M, int N, int K)
{
    extern __shared__ __half smh[];   // 3 stages x (A GSLAB + B GSLAB)

    const int tid  = threadIdx.x;
    const int lane = tid & 31;
    const int wid  = tid >> 5;
    const int wm   = wid & 1;
    const int wn   = wid >> 1;
    const int m0 = blockIdx.y * 128;
    const int n0 = blockIdx.x * 128;
    const int gid = lane >> 2;
    const int tig = lane & 3;

    const int aRow = lane & 15;
    const int aCol = (lane >> 4) << 3;
    const int bRow = ((lane >> 4) << 3) + (lane & 7);
    const int bCol = ((lane >> 3) & 1) << 3;

    auto load_slab = [&](int slab, int st) {
        const int k0 = slab * 64;
        const __half* Asrc = A  + (size_t)m0 * K + k0;
        const __half* Bsrc = Bm + (size_t)n0 * K + k0;
        __half* Ab = smh + st * (2 * GSLAB);
        __half* Bb = Ab + GSLAB;
#pragma unroll
        for (int l = 0; l < 4; l++) {
            int lin = tid + l * 256;     // 0..1023
            int r = lin >> 3;            // 0..127
            int u = lin & 7;
            cpa16(su32(Ab + r * FST + u * 8), Asrc + (size_t)r * K + u * 8);
            cpa16(su32(Bb + r * FST + u * 8), Bsrc + (size_t)r * K + u * 8);
        }
        CP_COMMIT();
    };

    float acc[4][4][4];
#pragma unroll
    for (int i = 0; i < 4; i++)
#pragma unroll
        for (int j = 0; j < 4; j++)
#pragma unroll
            for (int r = 0; r < 4; r++) acc[i][j][r] = 0.f;

    load_slab(0, 0); load_slab(1, 1); load_slab(2, 2);

    const int NIT = K / 64;
    for (int i = 0; i < NIT; i++) {
        const int st = i % 3;
        if (i <= NIT - 3)      { CP_WAIT2(); }
        else if (i == NIT - 2) { CP_WAIT1(); }
        else                   { CP_WAIT0(); }
        __syncthreads();
        const __half* Ac = smh + st * (2 * GSLAB);
        const __half* Bc = Ac + GSLAB;

        unsigned af[2][4][4];
#pragma unroll
        for (int mi = 0; mi < 4; mi++)
            ldm4(af[0][mi], su32(Ac + (wm * 64 + mi * 16 + aRow) * FST + aCol));

#pragma unroll
        for (int ks = 0; ks < 4; ks++) {
            unsigned bf[2][4];
#pragma unroll
            for (int nj = 0; nj < 2; nj++)
                ldm4(bf[nj], su32(Bc + (wn * 32 + nj * 16 + bRow) * FST + ks * 16 + bCol));
            if (ks < 3) {
#pragma unroll
                for (int mi = 0; mi < 4; mi++)
                    ldm4(af[(ks + 1) & 1][mi],
                         su32(Ac + (wm * 64 + mi * 16 + aRow) * FST + (ks + 1) * 16 + aCol));
            }
            const unsigned (*afc)[4] = af[ks & 1];
#pragma unroll
            for (int mi = 0; mi < 4; mi++)
#pragma unroll
                for (int ni = 0; ni < 4; ni++)
                    mma16h(acc[mi][ni], afc[mi], &bf[ni >> 1][(ni & 1) * 2]);
        }
        __syncthreads();
        if (i + 3 < NIT) load_slab(i + 3, st);
    }

#pragma unroll
    for (int mi = 0; mi < 4; mi++) {
        int m = m0 + wm * 64 + mi * 16 + gid;
#pragma unroll
        for (int ni = 0; ni < 4; ni++) {
            int n = n0 + wn * 32 + ni * 8 + 2 * tig;
            float bx = bias[n], by = bias[n + 1];
            if (HALF_OUT) {
                __half* C = (__half*)Cv;
                *(__half2*)(C + (size_t)m * N + n) =
                    __floats2half2_rn(acc[mi][ni][0] + bx, acc[mi][ni][1] + by);
                *(__half2*)(C + (size_t)(m + 8) * N + n) =
                    __floats2half2_rn(acc[mi][ni][2] + bx, acc[mi][ni][3] + by);
            } else {
                float* C = (float*)Cv;
                *(float2*)(C + (size_t)m * N + n) =
                    make_float2(acc[mi][ni][0] + bx, acc[mi][ni][1] + by);
                *(float2*)(C + (size_t)(m + 8) * N + n) =
                    make_float2(acc[mi][ni][2] + bx, acc[mi][ni][3] + by);
            }
        }
    }
}

// ---------------------------------------------------------------------------
// Flash attention, fp16 MMA (unchanged from R8 — known good).
// ---------------------------------------------------------------------------
__global__ void __launch_bounds__(256) flash_kernel(const float* __restrict__ td_ptr)
{
    extern __shared__ __half smh[];
    __half* Qs  = smh;
    __half* Ksb = smh + 128 * FST;
    __half* Vsb = Ksb + 2 * 64 * FST;

    const int tid  = threadIdx.x;
    const int lane = tid & 31;
    const int w    = tid >> 5;
    const int gid  = lane >> 2;
    const int tig  = lane & 3;
    const int bh = blockIdx.x;
    const int qt = blockIdx.y;
    const int b  = bh >> 4;
    const int h  = bh & 15;
    const float atd = fabsf(*td_ptr);
    const float scale = 0.125f;

    const int aRow = lane & 15;
    const int aCol = (lane >> 4) << 3;
    const int bRow = ((lane >> 4) << 3) + (lane & 7);
    const int bCol = ((lane >> 3) & 1) << 3;

    {
        const __half* qb = g_qkvh + (size_t)(b * S_ + qt * 128) * D3_ + h * HD_;
#pragma unroll
        for (int l = 0; l < 4; l++) {
            int lin = tid + l * 256;
            int r = lin >> 3;
            int u = lin & 7;
            cpa16(su32(Qs + r * FST + u * 8), qb + (size_t)r * D3_ + u * 8);
        }
    }
    auto issueKV = [&](int kt, int bf) {
        const __half* kb = g_qkvh + (size_t)(b * S_ + kt * 64) * D3_ + D_ + h * HD_;
        const __half* vb = kb + D_;
        __half* Kd = Ksb + bf * 64 * FST;
        __half* Vd = Vsb + bf * 64 * FST;
#pragma unroll
        for (int l = 0; l < 4; l++) {
            int lin = tid + l * 256;
            int r = lin >> 3;
            int u = lin & 7;
            if (r < 64)
                cpa16(su32(Kd + r * FST + u * 8), kb + (size_t)r * D3_ + u * 8);
            else
                cpa16(su32(Vd + (r - 64) * FST + u * 8), vb + (size_t)(r - 64) * D3_ + u * 8);
        }
        CP_COMMIT();
    };

    issueKV(0, 0);
    CP_WAIT0();
    __syncthreads();

    unsigned qf[4][4];
#pragma unroll
    for (int s = 0; s < 4; s++)
        ldm4(qf[s], su32(Qs + (w * 16 + aRow) * FST + s * 16 + aCol));

    float oacc[8][4];
#pragma unroll
    for (int n = 0; n < 8; n++)
#pragma unroll
        for (int r = 0; r < 4; r++) oacc[n][r] = 0.f;
    float ls0 = 0.f, ls1 = 0.f;

    const float qg0f = (float)(qt * 128 + w * 16 + gid);
    const float qg1f = qg0f + 8.f;

    for (int kt = 0; kt < 16; kt++) {
        CP_WAIT0();
        __syncthreads();
        if (kt < 15) issueKV(kt + 1, (kt + 1) & 1);
        const __half* Kc = Ksb + (kt & 1) * 64 * FST;
        const __half* Vc = Vsb + (kt & 1) * 64 * FST;

        float sacc[8][4];
#pragma unroll
        for (int n = 0; n < 8; n++)
#pragma unroll
            for (int r = 0; r < 4; r++) sacc[n][r] = 0.f;
#pragma unroll
        for (int s = 0; s < 4; s++) {
#pragma unroll
            for (int nj = 0; nj < 4; nj++) {
                unsigned kb[4];
                ldm4(kb, su32(Kc + (nj * 16 + bRow) * FST + s * 16 + bCol));
                mma16h(sacc[2 * nj],     qf[s], &kb[0]);
                mma16h(sacc[2 * nj + 1], qf[s], &kb[2]);
            }
        }

        unsigned pa[4][4];
#pragma unroll
        for (int nb = 0; nb < 8; nb++) {
            float c0 = (float)(kt * 64 + nb * 8 + 2 * tig);
            float p00 = __expf(sacc[nb][0] * scale - atd * fabsf(qg0f - c0));
            float p01 = __expf(sacc[nb][1] * scale - atd * fabsf(qg0f - c0 - 1.f));
            float p10 = __expf(sacc[nb][2] * scale - atd * fabsf(qg1f - c0));
            float p11 = __expf(sacc[nb][3] * scale - atd * fabsf(qg1f - c0 - 1.f));
            ls0 += p00 + p01; ls1 += p10 + p11;
            int j = nb >> 1;
            if ((nb & 1) == 0) {
                pa[j][0] = pkh2(p00, p01);
                pa[j][1] = pkh2(p10, p11);
            } else {
                pa[j][2] = pkh2(p00, p01);
                pa[j][3] = pkh2(p10, p11);
            }
        }

#pragma unroll
        for (int j = 0; j < 4; j++) {
#pragma unroll
            for (int nd = 0; nd < 4; nd++) {
                unsigned vb[4];
                ldm4t(vb, su32(Vc + (j * 16 + aRow) * FST + nd * 16 + aCol));
                mma16h(oacc[2 * nd],     pa[j], &vb[0]);
                mma16h(oacc[2 * nd + 1], pa[j], &vb[2]);
            }
        }
    }

#pragma unroll
    for (int o = 1; o <= 2; o <<= 1) {
        ls0 += __shfl_xor_sync(0xffffffffu, ls0, o);
        ls1 += __shfl_xor_sync(0xffffffffu, ls1, o);
    }
    float inv0 = 1.f / ls0, inv1 = 1.f / ls1;
    int t0 = b * S_ + qt * 128 + w * 16 + gid;
#pragma unroll
    for (int nb = 0; nb < 8; nb++) {
        int c = h * HD_ + nb * 8 + 2 * tig;
        *(__half2*)&g_attnh[(size_t)t0 * D_ + c] =
            __floats2half2_rn(oacc[nb][0] * inv0, oacc[nb][1] * inv0);
        *(__half2*)&g_attnh[(size_t)(t0 + 8) * D_ + c] =
            __floats2half2_rn(oacc[nb][2] * inv1, oacc[nb][3] * inv1);
    }
    if (tig == 0) {
        int si = (b * H_ + h) * S_ + qt * 128 + w * 16 + gid;
        g_linv[si] = inv0;
        g_linv[si + 8] = inv1;
    }
}

// ---------------------------------------------------------------------------
// Head-mean weights, fp16 MMA (unchanged from R8 — known good).
// ---------------------------------------------------------------------------
__global__ void __launch_bounds__(128) weights_kernel(
    const float* __restrict__ td_ptr, float* __restrict__ wout)
{
    extern __shared__ __half smh[];
    __half* Qb = smh;
    __half* Kb = smh + 2 * 64 * FST;
    float*  lsb = (float*)(smh + 4 * 64 * FST);

    const int tid  = threadIdx.x;
    const int lane = tid & 31;
    const int wid  = tid >> 5;
    const int qt = blockIdx.x;
    const int b  = blockIdx.y;
    const int kt = blockIdx.z;
    const float atd = fabsf(*td_ptr);
    const float scale = 0.125f;
    const int gid = lane >> 2;
    const int tig = lane & 3;

    const int aRow = lane & 15;
    const int aCol = (lane >> 4) << 3;
    const int bRow = ((lane >> 4) << 3) + (lane & 7);
    const int bCol = ((lane >> 3) & 1) << 3;

    auto issue = [&](int h, int bf) {
        const __half* qb = g_qkvh + (size_t)(b * S_ + qt * 64) * D3_ + h * HD_;
        const __half* kb = g_qkvh + (size_t)(b * S_ + kt * 64) * D3_ + D_ + h * HD_;
        __half* Qd = Qb + bf * 64 * FST;
        __half* Kd = Kb + bf * 64 * FST;
#pragma unroll
        for (int l = 0; l < 8; l++) {
            int lin = tid + l * 128;
            int r = lin >> 3;
            int u = lin & 7;
            if (r < 64)
                cpa16(su32(Qd + r * FST + u * 8), qb + (size_t)r * D3_ + u * 8);
            else
                cpa16(su32(Kd + (r - 64) * FST + u * 8), kb + (size_t)(r - 64) * D3_ + u * 8);
        }
        CP_COMMIT();
    };

    issue(0, 0);
    {
        int si0 = (b * H_ + 0) * S_ + qt * 64;
        if (tid < 64) lsb[tid] = g_linv[si0 + tid];
    }

    float wsum[4][2][4];
#pragma unroll
    for (int mi = 0; mi < 4; mi++)
#pragma unroll
        for (int ni = 0; ni < 2; ni++)
#pragma unroll
            for (int r = 0; r < 4; r++) wsum[mi][ni][r] = 0.f;

    for (int h = 0; h < H_; h++) {
        const int bf = h & 1;
        CP_WAIT0();
        __syncthreads();
        if (h < 15) {
            issue(h + 1, bf ^ 1);
            int si0 = (b * H_ + h + 1) * S_ + qt * 64;
            if (tid < 64) lsb[(bf ^ 1) * 64 + tid] = g_linv[si0 + tid];
        }
        const __half* Qc = Qb + bf * 64 * FST;
        const __half* Kc = Kb + bf * 64 * FST;
        const float* ls = lsb + bf * 64;

        float acc[4][2][4];
#pragma unroll
        for (int mi = 0; mi < 4; mi++)
#pragma unroll
            for (int ni = 0; ni < 2; ni++)
#pragma unroll
                for (int r = 0; r < 4; r++) acc[mi][ni][r] = 0.f;

#pragma unroll
        for (int ks = 0; ks < 4; ks++) {
            unsigned bfr[4];
            ldm4(bfr, su32(Kc + (wid * 16 + bRow) * FST + ks * 16 + bCol));
#pragma unroll
            for (int mi = 0; mi < 4; mi++) {
                unsigned af[4];
                ldm4(af, su32(Qc + (mi * 16 + aRow) * FST + ks * 16 + aCol));
                mma16h(acc[mi][0], af, &bfr[0]);
                mma16h(acc[mi][1], af, &bfr[2]);
            }
        }

#pragma unroll
        for (int mi = 0; mi < 4; mi++) {
            int r0 = mi * 16 + gid;
            int r1 = r0 + 8;
            int qg0 = qt * 64 + r0;
            int qg1 = qt * 64 + r1;
            float l0v = ls[r0], l1v = ls[r1];
#pragma unroll
            for (int ni = 0; ni < 2; ni++) {
                int c0 = kt * 64 + wid * 16 + ni * 8 + 2 * tig;
                float v;
                v = acc[mi][ni][0] * scale - atd * fabsf((float)(qg0 - c0));
                wsum[mi][ni][0] += __expf(v) * l0v;
                v = acc[mi][ni][1] * scale - atd * fabsf((float)(qg0 - c0 - 1));
                wsum[mi][ni][1] += __expf(v) * l0v;
                v = acc[mi][ni][2] * scale - atd * fabsf((float)(qg1 - c0));
                wsum[mi][ni][2] += __expf(v) * l1v;
                v = acc[mi][ni][3] * scale - atd * fabsf((float)(qg1 - c0 - 1));
                wsum[mi][ni][3] += __expf(v) * l1v;
            }
        }
    }

    const float inv_h = 1.0f / (float)H_;
#pragma unroll
    for (int mi = 0; mi < 4; mi++) {
        int r0 = qt * 64 + mi * 16 + gid;
#pragma unroll
        for (int ni = 0; ni < 2; ni++) {
            int c = kt * 64 + wid * 16 + ni * 8 + 2 * tig;
            float2 o0 = make_float2(wsum[mi][ni][0] * inv_h, wsum[mi][ni][1] * inv_h);
            float2 o1 = make_float2(wsum[mi][ni][2] * inv_h, wsum[mi][ni][3] * inv_h);
            *(float2*)(wout + (size_t)(b * S_ + r0) * S_ + c) = o0;
            *(float2*)(wout + (size_t)(b * S_ + r0 + 8) * S_ + c) = o1;
        }
    }
}

// ---------------------------------------------------------------------------
// Residual + LayerNorm
// ---------------------------------------------------------------------------
__global__ void __launch_bounds__(256) ln_kernel(
    const float* __restrict__ x, const float* __restrict__ lnw,
    const float* __restrict__ lnb, float* __restrict__ out)
{
    const int row = blockIdx.x;
    const int tid = threadIdx.x;
    const float* xr = x + (size_t)row * D_;
    const float* ar = g_attnout + (size_t)row * D_;

    float4 xv = *(const float4*)(xr + tid * 4);
    float4 av = *(const float4*)(ar + tid * 4);
    float y[4];
    y[0] = xv.x + av.x; y[1] = xv.y + av.y;
    y[2] = xv.z + av.z; y[3] = xv.w + av.w;

    float s  = y[0] + y[1] + y[2] + y[3];
    float sq = y[0]*y[0] + y[1]*y[1] + y[2]*y[2] + y[3]*y[3];
#pragma unroll
    for (int o = 16; o >= 1; o >>= 1) {
        s  += __shfl_xor_sync(0xffffffffu, s,  o);
        sq += __shfl_xor_sync(0xffffffffu, sq, o);
    }
    __shared__ float red[16];
    const int wid = tid >> 5;
    if ((tid & 31) == 0) { red[wid] = s; red[8 + wid] = sq; }
    __syncthreads();
    float st = 0.f, sqt = 0.f;
#pragma unroll
    for (int w = 0; w < 8; w++) { st += red[w]; sqt += red[8 + w]; }
    float mu = st * (1.0f / D_);
    float var = sqt * (1.0f / D_) - mu * mu;
    float rstd = rsqrtf(var + 1e-5f);

    float4 wv = *(const float4*)(lnw + tid * 4);
    float4 bv = *(const float4*)(lnb + tid * 4);
    float4 o4;
    o4.x = (y[0] - mu) * rstd * wv.x + bv.x;
    o4.y = (y[1] - mu) * rstd * wv.y + bv.y;
    o4.z = (y[2] - mu) * rstd * wv.z + bv.z;
    o4.w = (y[3] - mu) * rstd * wv.w + bv.w;
    *(float4*)(out + (size_t)row * D_ + tid * 4) = o4;
}

// ---------------------------------------------------------------------------
extern "C" void kernel_launch(void* const* d_in, const int* in_sizes, int n_in,
                              void* d_out, int out_size)
{
    (void)in_sizes; (void)n_in; (void)out_size;
    const float* x     = (const float*)d_in[0];
    const float* td    = (const float*)d_in[1];
    const float* in_w  = (const float*)d_in[2];
    const float* in_b  = (const float*)d_in[3];
    const float* out_w = (const float*)d_in[4];
    const float* out_b = (const float*)d_in[5];
    const float* lnw   = (const float*)d_in[6];
    const float* lnb   = (const float*)d_in[7];
    float* out  = (float*)d_out;
    float* wout = out + (size_t)T_ * D_;

    float *attnout_p;
    __half *xh_p, *wih_p, *woh_p, *attnh_p, *qkvh_p;
    cudaGetSymbolAddress((void**)&attnout_p, g_attnout);
    cudaGetSymbolAddress((void**)&xh_p, g_xh);
    cudaGetSymbolAddress((void**)&wih_p, g_wih);
    cudaGetSymbolAddress((void**)&woh_p, g_woh);
    cudaGetSymbolAddress((void**)&attnh_p, g_attnh);
    cudaGetSymbolAddress((void**)&qkvh_p, g_qkvh);

    const int gsmem = 3 * 2 * GSLAB * 2;                     // 110592 B
    const int fsmem = (128 * FST + 4 * 64 * FST) * 2;        // 55296 B
    const int wsmem = 4 * 64 * FST * 2 + 2 * 64 * 4;         // 37376 B
    cudaFuncSetAttribute(gemm_hf_kernel<true>,
                         cudaFuncAttributeMaxDynamicSharedMemorySize, gsmem);
    cudaFuncSetAttribute(gemm_hf_kernel<false>,
                         cudaFuncAttributeMaxDynamicSharedMemorySize, gsmem);
    cudaFuncSetAttribute(flash_kernel,
                         cudaFuncAttributeMaxDynamicSharedMemorySize, fsmem);
    cudaFuncSetAttribute(weights_kernel,
                         cudaFuncAttributeMaxDynamicSharedMemorySize, wsmem);

    // 0. Convert GEMM inputs to fp16
    {
        int n4;
        n4 = (T_ * D_) / 4;
        to_half_kernel<<<(n4 + 255) / 256, 256>>>(x, xh_p, n4);
        n4 = (D3_ * D_) / 4;
        to_half_kernel<<<(n4 + 255) / 256, 256>>>(in_w, wih_p, n4);
        n4 = (D_ * D_) / 4;
        to_half_kernel<<<(n4 + 255) / 256, 256>>>(out_w, woh_p, n4);
    }

    // 1. QKV projection -> fp16 qkv
    gemm_hf_kernel<true><<<dim3(3 * D_ / 128, T_ / 128), 256, gsmem>>>(
        xh_p, wih_p, in_b, qkvh_p, T_, 3 * D_, D_);

    // 2. Flash attention (fp16 MMA) -> g_attnh, g_linv
    flash_kernel<<<dim3(B_ * H_, S_ / 128), 256, fsmem>>>(td);

    // 3. Head-mean weights (fp16 MMA) -> second output
    weights_kernel<<<dim3(S_ / 64, B_, S_ / 64), 128, wsmem>>>(td, wout);

    // 4. Out projection (fp32 output)
    gemm_hf_kernel<false><<<dim3(D_ / 128, T_ / 128), 256, gsmem>>>(
        attnh_p, woh_p, out_b, attnout_p, T_, D_, D_);

    // 5. Residual + LayerNorm
    ln_kernel<<<T_, 256>>>(x, lnw, lnb, out);
}

// round 11
// speedup vs baseline: 2.3556x; 1.0275x over previous
#include <cuda_runtime.h>
#include <cuda_fp16.h>
#include <cstdint>

// Problem constants
#define S_   1024
#define B_   8
#define D_   1024
#define H_   16
#define HD_  64
#define T_   (B_ * S_)
#define D3_  (3 * D_)

// Scratch
__device__ __half g_qkvh[(size_t)T_ * 3 * D_];
__device__ __half g_attnh[(size_t)T_ * D_];
__device__ float  g_attnout[(size_t)T_ * D_];
__device__ float  g_linv[B_ * H_ * S_];
__device__ __half g_xh[(size_t)T_ * D_];
__device__ __half g_wih[(size_t)D3_ * D_];
__device__ __half g_woh[(size_t)D_ * D_];

__device__ __forceinline__ unsigned su32(const void* p) {
    return (unsigned)__cvta_generic_to_shared(p);
}
__device__ __forceinline__ void cpa16(unsigned dst, const void* src) {
    asm volatile("cp.async.cg.shared.global [%0], [%1], 16;" :: "r"(dst), "l"(src));
}
#define CP_COMMIT() asm volatile("cp.async.commit_group;")
#define CP_WAIT0()  asm volatile("cp.async.wait_group 0;")
#define CP_WAIT1()  asm volatile("cp.async.wait_group 1;")

__device__ __forceinline__ unsigned pkh2(float a, float b) {
    __half2 h = __floats2half2_rn(a, b);
    return *(unsigned*)&h;
}

// fp16 m16n8k16
__device__ __forceinline__ void mma16h(float* d, const unsigned* a, const unsigned* b) {
    asm volatile(
        "mma.sync.aligned.m16n8k16.row.col.f32.f16.f16.f32 "
        "{%0,%1,%2,%3},{%4,%5,%6,%7},{%8,%9},{%0,%1,%2,%3};"
        : "+f"(d[0]), "+f"(d[1]), "+f"(d[2]), "+f"(d[3])
        : "r"(a[0]), "r"(a[1]), "r"(a[2]), "r"(a[3]), "r"(b[0]), "r"(b[1]));
}
__device__ __forceinline__ void ldm4(unsigned* r, unsigned addr) {
    asm volatile("ldmatrix.sync.aligned.m8n8.x4.shared.b16 {%0,%1,%2,%3}, [%4];"
        : "=r"(r[0]), "=r"(r[1]), "=r"(r[2]), "=r"(r[3]) : "r"(addr));
}
__device__ __forceinline__ void ldm4t(unsigned* r, unsigned addr) {
    asm volatile("ldmatrix.sync.aligned.m8n8.x4.trans.shared.b16 {%0,%1,%2,%3}, [%4];"
        : "=r"(r[0]), "=r"(r[1]), "=r"(r[2]), "=r"(r[3]) : "r"(addr));
}

// ---------------------------------------------------------------------------
// fp32 -> fp16 conversion
// ---------------------------------------------------------------------------
__global__ void __launch_bounds__(256) to_half_kernel(
    const float* __restrict__ src, __half* __restrict__ dst, int n4)
{
    int i = blockIdx.x * blockDim.x + threadIdx.x;
    if (i < n4) {
        float4 v = ((const float4*)src)[i];
        ((__half2*)dst)[2 * i]     = __floats2half2_rn(v.x, v.y);
        ((__half2*)dst)[2 * i + 1] = __floats2half2_rn(v.z, v.w);
    }
}

// ---------------------------------------------------------------------------
// fp16 GEMM: C[M,N] = A[M,K] @ B[N,K]^T + bias[N]
// 128x128 tile, 128 threads (4 warps, 2x2, warp tile 64x64).
// BK=64 slabs (stride FST=72, conflict-free), 3-stage cp.async,
// prefetch distance 2 -> ONE barrier per iteration.
// ---------------------------------------------------------------------------
#define FST 72
#define GSLAB (128 * FST)            // halves per operand slab
template<bool HALF_OUT>
__global__ void __launch_bounds__(128) gemm_hf_kernel(
    const __half* __restrict__ A, const __half* __restrict__ Bm,
    const float* __restrict__ bias, void* __restrict__ Cv,
    int M, int N, int K)
{
    extern __shared__ __half smh[];   // 3 stages x (A GSLAB + B GSLAB)

    const int tid  = threadIdx.x;
    const int lane = tid & 31;
    const int wid  = tid >> 5;        // 0..3
    const int wm   = wid >> 1;        // 0..1
    const int wn   = wid & 1;         // 0..1
    const int m0 = blockIdx.y * 128;
    const int n0 = blockIdx.x * 128;
    const int gid = lane >> 2;
    const int tig = lane & 3;

    const int aRow = lane & 15;
    const int aCol = (lane >> 4) << 3;
    const int bRow = ((lane >> 4) << 3) + (lane & 7);
    const int bCol = ((lane >> 3) & 1) << 3;

    auto load_slab = [&](int slab, int st) {
        const int k0 = slab * 64;
        const __half* Asrc = A  + (size_t)m0 * K + k0;
        const __half* Bsrc = Bm + (size_t)n0 * K + k0;
        __half* Ab = smh + st * (2 * GSLAB);
        __half* Bb = Ab + GSLAB;
#pragma unroll
        for (int l = 0; l < 8; l++) {
            int lin = tid + l * 128;     // 0..1023
            int r = lin >> 3;            // 0..127
            int u = lin & 7;
            cpa16(su32(Ab + r * FST + u * 8), Asrc + (size_t)r * K + u * 8);
            cpa16(su32(Bb + r * FST + u * 8), Bsrc + (size_t)r * K + u * 8);
        }
        CP_COMMIT();
    };

    float acc[4][8][4];
#pragma unroll
    for (int i = 0; i < 4; i++)
#pragma unroll
        for (int j = 0; j < 8; j++)
#pragma unroll
            for (int r = 0; r < 4; r++) acc[i][j][r] = 0.f;

    load_slab(0, 0); load_slab(1, 1);

    const int NIT = K / 64;
    for (int i = 0; i < NIT; i++) {
        const int st = i % 3;
        if (i + 1 < NIT) { CP_WAIT1(); } else { CP_WAIT0(); }
        __syncthreads();                 // slab i ready; stage (i+2)%3 free
        if (i + 2 < NIT) load_slab(i + 2, (i + 2) % 3);

        const __half* Ac = smh + st * (2 * GSLAB);
        const __half* Bc = Ac + GSLAB;

#pragma unroll
        for (int ks = 0; ks < 4; ks++) {
            unsigned af[4][4], bf[4][4];
#pragma unroll
            for (int mi = 0; mi < 4; mi++)
                ldm4(af[mi], su32(Ac + (wm * 64 + mi * 16 + aRow) * FST + ks * 16 + aCol));
#pragma unroll
            for (int nj = 0; nj < 4; nj++)
                ldm4(bf[nj], su32(Bc + (wn * 64 + nj * 16 + bRow) * FST + ks * 16 + bCol));
#pragma unroll
            for (int mi = 0; mi < 4; mi++)
#pragma unroll
                for (int ni = 0; ni < 8; ni++)
                    mma16h(acc[mi][ni], af[mi], &bf[ni >> 1][(ni & 1) * 2]);
        }
    }

#pragma unroll
    for (int mi = 0; mi < 4; mi++) {
        int m = m0 + wm * 64 + mi * 16 + gid;
#pragma unroll
        for (int ni = 0; ni < 8; ni++) {
            int n = n0 + wn * 64 + ni * 8 + 2 * tig;
            float bx = bias[n], by = bias[n + 1];
            if (HALF_OUT) {
                __half* C = (__half*)Cv;
                *(__half2*)(C + (size_t)m * N + n) =
                    __floats2half2_rn(acc[mi][ni][0] + bx, acc[mi][ni][1] + by);
                *(__half2*)(C + (size_t)(m + 8) * N + n) =
                    __floats2half2_rn(acc[mi][ni][2] + bx, acc[mi][ni][3] + by);
            } else {
                float* C = (float*)Cv;
                *(float2*)(C + (size_t)m * N + n) =
                    make_float2(acc[mi][ni][0] + bx, acc[mi][ni][1] + by);
                *(float2*)(C + (size_t)(m + 8) * N + n) =
                    make_float2(acc[mi][ni][2] + bx, acc[mi][ni][3] + by);
            }
        }
    }
}

// ---------------------------------------------------------------------------
// Flash attention, fp16 MMA (unchanged — known good).
// ---------------------------------------------------------------------------
__global__ void __launch_bounds__(256) flash_kernel(const float* __restrict__ td_ptr)
{
    extern __shared__ __half smh[];
    __half* Qs  = smh;
    __half* Ksb = smh + 128 * FST;
    __half* Vsb = Ksb + 2 * 64 * FST;

    const int tid  = threadIdx.x;
    const int lane = tid & 31;
    const int w    = tid >> 5;
    const int gid  = lane >> 2;
    const int tig  = lane & 3;
    const int bh = blockIdx.x;
    const int qt = blockIdx.y;
    const int b  = bh >> 4;
    const int h  = bh & 15;
    const float atd = fabsf(*td_ptr);
    const float scale = 0.125f;

    const int aRow = lane & 15;
    const int aCol = (lane >> 4) << 3;
    const int bRow = ((lane >> 4) << 3) + (lane & 7);
    const int bCol = ((lane >> 3) & 1) << 3;

    {
        const __half* qb = g_qkvh + (size_t)(b * S_ + qt * 128) * D3_ + h * HD_;
#pragma unroll
        for (int l = 0; l < 4; l++) {
            int lin = tid + l * 256;
            int r = lin >> 3;
            int u = lin & 7;
            cpa16(su32(Qs + r * FST + u * 8), qb + (size_t)r * D3_ + u * 8);
        }
    }
    auto issueKV = [&](int kt, int bf) {
        const __half* kb = g_qkvh + (size_t)(b * S_ + kt * 64) * D3_ + D_ + h * HD_;
        const __half* vb = kb + D_;
        __half* Kd = Ksb + bf * 64 * FST;
        __half* Vd = Vsb + bf * 64 * FST;
#pragma unroll
        for (int l = 0; l < 4; l++) {
            int lin = tid + l * 256;
            int r = lin >> 3;
            int u = lin & 7;
            if (r < 64)
                cpa16(su32(Kd + r * FST + u * 8), kb + (size_t)r * D3_ + u * 8);
            else
                cpa16(su32(Vd + (r - 64) * FST + u * 8), vb + (size_t)(r - 64) * D3_ + u * 8);
        }
        CP_COMMIT();
    };

    issueKV(0, 0);
    CP_WAIT0();
    __syncthreads();

    unsigned qf[4][4];
#pragma unroll
    for (int s = 0; s < 4; s++)
        ldm4(qf[s], su32(Qs + (w * 16 + aRow) * FST + s * 16 + aCol));

    float oacc[8][4];
#pragma unroll
    for (int n = 0; n < 8; n++)
#pragma unroll
        for (int r = 0; r < 4; r++) oacc[n][r] = 0.f;
    float ls0 = 0.f, ls1 = 0.f;

    const float qg0f = (float)(qt * 128 + w * 16 + gid);
    const float qg1f = qg0f + 8.f;

    for (int kt = 0; kt < 16; kt++) {
        CP_WAIT0();
        __syncthreads();
        if (kt < 15) issueKV(kt + 1, (kt + 1) & 1);
        const __half* Kc = Ksb + (kt & 1) * 64 * FST;
        const __half* Vc = Vsb + (kt & 1) * 64 * FST;

        float sacc[8][4];
#pragma unroll
        for (int n = 0; n < 8; n++)
#pragma unroll
            for (int r = 0; r < 4; r++) sacc[n][r] = 0.f;
#pragma unroll
        for (int s = 0; s < 4; s++) {
#pragma unroll
            for (int nj = 0; nj < 4; nj++) {
                unsigned kb[4];
                ldm4(kb, su32(Kc + (nj * 16 + bRow) * FST + s * 16 + bCol));
                mma16h(sacc[2 * nj],     qf[s], &kb[0]);
                mma16h(sacc[2 * nj + 1], qf[s], &kb[2]);
            }
        }

        unsigned pa[4][4];
#pragma unroll
        for (int nb = 0; nb < 8; nb++) {
            float c0 = (float)(kt * 64 + nb * 8 + 2 * tig);
            float p00 = __expf(sacc[nb][0] * scale - atd * fabsf(qg0f - c0));
            float p01 = __expf(sacc[nb][1] * scale - atd * fabsf(qg0f - c0 - 1.f));
            float p10 = __expf(sacc[nb][2] * scale - atd * fabsf(qg1f - c0));
            float p11 = __expf(sacc[nb][3] * scale - atd * fabsf(qg1f - c0 - 1.f));
            ls0 += p00 + p01; ls1 += p10 + p11;
            int j = nb >> 1;
            if ((nb & 1) == 0) {
                pa[j][0] = pkh2(p00, p01);
                pa[j][1] = pkh2(p10, p11);
            } else {
                pa[j][2] = pkh2(p00, p01);
                pa[j][3] = pkh2(p10, p11);
            }
        }

#pragma unroll
        for (int j = 0; j < 4; j++) {
#pragma unroll
            for (int nd = 0; nd < 4; nd++) {
                unsigned vb[4];
                ldm4t(vb, su32(Vc + (j * 16 + aRow) * FST + nd * 16 + aCol));
                mma16h(oacc[2 * nd],     pa[j], &vb[0]);
                mma16h(oacc[2 * nd + 1], pa[j], &vb[2]);
            }
        }
    }

#pragma unroll
    for (int o = 1; o <= 2; o <<= 1) {
        ls0 += __shfl_xor_sync(0xffffffffu, ls0, o);
        ls1 += __shfl_xor_sync(0xffffffffu, ls1, o);
    }
    float inv0 = 1.f / ls0, inv1 = 1.f / ls1;
    int t0 = b * S_ + qt * 128 + w * 16 + gid;
#pragma unroll
    for (int nb = 0; nb < 8; nb++) {
        int c = h * HD_ + nb * 8 + 2 * tig;
        *(__half2*)&g_attnh[(size_t)t0 * D_ + c] =
            __floats2half2_rn(oacc[nb][0] * inv0, oacc[nb][1] * inv0);
        *(__half2*)&g_attnh[(size_t)(t0 + 8) * D_ + c] =
            __floats2half2_rn(oacc[nb][2] * inv1, oacc[nb][3] * inv1);
    }
    if (tig == 0) {
        int si = (b * H_ + h) * S_ + qt * 128 + w * 16 + gid;
        g_linv[si] = inv0;
        g_linv[si + 8] = inv1;
    }
}

// ---------------------------------------------------------------------------
// Head-mean weights, fp16 MMA (unchanged — known good).
// ---------------------------------------------------------------------------
__global__ void __launch_bounds__(128) weights_kernel(
    const float* __restrict__ td_ptr, float* __restrict__ wout)
{
    extern __shared__ __half smh[];
    __half* Qb = smh;
    __half* Kb = smh + 2 * 64 * FST;
    float*  lsb = (float*)(smh + 4 * 64 * FST);

    const int tid  = threadIdx.x;
    const int lane = tid & 31;
    const int wid  = tid >> 5;
    const int qt = blockIdx.x;
    const int b  = blockIdx.y;
    const int kt = blockIdx.z;
    const float atd = fabsf(*td_ptr);
    const float scale = 0.125f;
    const int gid = lane >> 2;
    const int tig = lane & 3;

    const int aRow = lane & 15;
    const int aCol = (lane >> 4) << 3;
    const int bRow = ((lane >> 4) << 3) + (lane & 7);
    const int bCol = ((lane >> 3) & 1) << 3;

    auto issue = [&](int h, int bf) {
        const __half* qb = g_qkvh + (size_t)(b * S_ + qt * 64) * D3_ + h * HD_;
        const __half* kb = g_qkvh + (size_t)(b * S_ + kt * 64) * D3_ + D_ + h * HD_;
        __half* Qd = Qb + bf * 64 * FST;
        __half* Kd = Kb + bf * 64 * FST;
#pragma unroll
        for (int l = 0; l < 8; l++) {
            int lin = tid + l * 128;
            int r = lin >> 3;
            int u = lin & 7;
            if (r < 64)
                cpa16(su32(Qd + r * FST + u * 8), qb + (size_t)r * D3_ + u * 8);
            else
                cpa16(su32(Kd + (r - 64) * FST + u * 8), kb + (size_t)(r - 64) * D3_ + u * 8);
        }
        CP_COMMIT();
    };

    issue(0, 0);
    {
        int si0 = (b * H_ + 0) * S_ + qt * 64;
        if (tid < 64) lsb[tid] = g_linv[si0 + tid];
    }

    float wsum[4][2][4];
#pragma unroll
    for (int mi = 0; mi < 4; mi++)
#pragma unroll
        for (int ni = 0; ni < 2; ni++)
#pragma unroll
            for (int r = 0; r < 4; r++) wsum[mi][ni][r] = 0.f;

    for (int h = 0; h < H_; h++) {
        const int bf = h & 1;
        CP_WAIT0();
        __syncthreads();
        if (h < 15) {
            issue(h + 1, bf ^ 1);
            int si0 = (b * H_ + h + 1) * S_ + qt * 64;
            if (tid < 64) lsb[(bf ^ 1) * 64 + tid] = g_linv[si0 + tid];
        }
        const __half* Qc = Qb + bf * 64 * FST;
        const __half* Kc = Kb + bf * 64 * FST;
        const float* ls = lsb + bf * 64;

        float acc[4][2][4];
#pragma unroll
        for (int mi = 0; mi < 4; mi++)
#pragma unroll
            for (int ni = 0; ni < 2; ni++)
#pragma unroll
                for (int r = 0; r < 4; r++) acc[mi][ni][r] = 0.f;

#pragma unroll
        for (int ks = 0; ks < 4; ks++) {
            unsigned bfr[4];
            ldm4(bfr, su32(Kc + (wid * 16 + bRow) * FST + ks * 16 + bCol));
#pragma unroll
            for (int mi = 0; mi < 4; mi++) {
                unsigned af[4];
                ldm4(af, su32(Qc + (mi * 16 + aRow) * FST + ks * 16 + aCol));
                mma16h(acc[mi][0], af, &bfr[0]);
                mma16h(acc[mi][1], af, &bfr[2]);
            }
        }

#pragma unroll
        for (int mi = 0; mi < 4; mi++) {
            int r0 = mi * 16 + gid;
            int r1 = r0 + 8;
            int qg0 = qt * 64 + r0;
            int qg1 = qt * 64 + r1;
            float l0v = ls[r0], l1v = ls[r1];
#pragma unroll
            for (int ni = 0; ni < 2; ni++) {
                int c0 = kt * 64 + wid * 16 + ni * 8 + 2 * tig;
                float v;
                v = acc[mi][ni][0] * scale - atd * fabsf((float)(qg0 - c0));
                wsum[mi][ni][0] += __expf(v) * l0v;
                v = acc[mi][ni][1] * scale - atd * fabsf((float)(qg0 - c0 - 1));
                wsum[mi][ni][1] += __expf(v) * l0v;
                v = acc[mi][ni][2] * scale - atd * fabsf((float)(qg1 - c0));
                wsum[mi][ni][2] += __expf(v) * l1v;
                v = acc[mi][ni][3] * scale - atd * fabsf((float)(qg1 - c0 - 1));
                wsum[mi][ni][3] += __expf(v) * l1v;
            }
        }
    }

    const float inv_h = 1.0f / (float)H_;
#pragma unroll
    for (int mi = 0; mi < 4; mi++) {
        int r0 = qt * 64 + mi * 16 + gid;
#pragma unroll
        for (int ni = 0; ni < 2; ni++) {
            int c = kt * 64 + wid * 16 + ni * 8 + 2 * tig;
            float2 o0 = make_float2(wsum[mi][ni][0] * inv_h, wsum[mi][ni][1] * inv_h);
            float2 o1 = make_float2(wsum[mi][ni][2] * inv_h, wsum[mi][ni][3] * inv_h);
            *(float2*)(wout + (size_t)(b * S_ + r0) * S_ + c) = o0;
            *(float2*)(wout + (size_t)(b * S_ + r0 + 8) * S_ + c) = o1;
        }
    }
}

// ---------------------------------------------------------------------------
// Residual + LayerNorm
// ---------------------------------------------------------------------------
__global__ void __launch_bounds__(256) ln_kernel(
    const float* __restrict__ x, const float* __restrict__ lnw,
    const float* __restrict__ lnb, float* __restrict__ out)
{
    const int row = blockIdx.x;
    const int tid = threadIdx.x;
    const float* xr = x + (size_t)row * D_;
    const float* ar = g_attnout + (size_t)row * D_;

    float4 xv = *(const float4*)(xr + tid * 4);
    float4 av = *(const float4*)(ar + tid * 4);
    float y[4];
    y[0] = xv.x + av.x; y[1] = xv.y + av.y;
    y[2] = xv.z + av.z; y[3] = xv.w + av.w;

    float s  = y[0] + y[1] + y[2] + y[3];
    float sq = y[0]*y[0] + y[1]*y[1] + y[2]*y[2] + y[3]*y[3];
#pragma unroll
    for (int o = 16; o >= 1; o >>= 1) {
        s  += __shfl_xor_sync(0xffffffffu, s,  o);
        sq += __shfl_xor_sync(0xffffffffu, sq, o);
    }
    __shared__ float red[16];
    const int wid = tid >> 5;
    if ((tid & 31) == 0) { red[wid] = s; red[8 + wid] = sq; }
    __syncthreads();
    float st = 0.f, sqt = 0.f;
#pragma unroll
    for (int w = 0; w < 8; w++) { st += red[w]; sqt += red[8 + w]; }
    float mu = st * (1.0f / D_);
    float var = sqt * (1.0f / D_) - mu * mu;
    float rstd = rsqrtf(var + 1e-5f);

    float4 wv = *(const float4*)(lnw + tid * 4);
    float4 bv = *(const float4*)(lnb + tid * 4);
    float4 o4;
    o4.x = (y[0] - mu) * rstd * wv.x + bv.x;
    o4.y = (y[1] - mu) * rstd * wv.y + bv.y;
    o4.z = (y[2] - mu) * rstd * wv.z + bv.z;
    o4.w = (y[3] - mu) * rstd * wv.w + bv.w;
    *(float4*)(out + (size_t)row * D_ + tid * 4) = o4;
}

// ---------------------------------------------------------------------------
extern "C" void kernel_launch(void* const* d_in, const int* in_sizes, int n_in,
                              void* d_out, int out_size)
{
    (void)in_sizes; (void)n_in; (void)out_size;
    const float* x     = (const float*)d_in[0];
    const float* td    = (const float*)d_in[1];
    const float* in_w  = (const float*)d_in[2];
    const float* in_b  = (const float*)d_in[3];
    const float* out_w = (const float*)d_in[4];
    const float* out_b = (const float*)d_in[5];
    const float* lnw   = (const float*)d_in[6];
    const float* lnb   = (const float*)d_in[7];
    float* out  = (float*)d_out;
    float* wout = out + (size_t)T_ * D_;

    float *attnout_p;
    __half *xh_p, *wih_p, *woh_p, *attnh_p, *qkvh_p;
    cudaGetSymbolAddress((void**)&attnout_p, g_attnout);
    cudaGetSymbolAddress((void**)&xh_p, g_xh);
    cudaGetSymbolAddress((void**)&wih_p, g_wih);
    cudaGetSymbolAddress((void**)&woh_p, g_woh);
    cudaGetSymbolAddress((void**)&attnh_p, g_attnh);
    cudaGetSymbolAddress((void**)&qkvh_p, g_qkvh);

    const int gsmem = 3 * 2 * GSLAB * 2;                     // 110592 B
    const int fsmem = (128 * FST + 4 * 64 * FST) * 2;        // 55296 B
    const int wsmem = 4 * 64 * FST * 2 + 2 * 64 * 4;         // 37376 B
    cudaFuncSetAttribute(gemm_hf_kernel<true>,
                         cudaFuncAttributeMaxDynamicSharedMemorySize, gsmem);
    cudaFuncSetAttribute(gemm_hf_kernel<false>,
                         cudaFuncAttributeMaxDynamicSharedMemorySize, gsmem);
    cudaFuncSetAttribute(flash_kernel,
                         cudaFuncAttributeMaxDynamicSharedMemorySize, fsmem);
    cudaFuncSetAttribute(weights_kernel,
                         cudaFuncAttributeMaxDynamicSharedMemorySize, wsmem);

    // 0. Convert GEMM inputs to fp16
    {
        int n4;
        n4 = (T_ * D_) / 4;
        to_half_kernel<<<(n4 + 255) / 256, 256>>>(x, xh_p, n4);
        n4 = (D3_ * D_) / 4;
        to_half_kernel<<<(n4 + 255) / 256, 256>>>(in_w, wih_p, n4);
        n4 = (D_ * D_) / 4;
        to_half_kernel<<<(n4 + 255) / 256, 256>>>(out_w, woh_p, n4);
    }

    // 1. QKV projection -> fp16 qkv
    gemm_hf_kernel<true><<<dim3(3 * D_ / 128, T_ / 128), 128, gsmem>>>(
        xh_p, wih_p, in_b, qkvh_p, T_, 3 * D_, D_);

    // 2. Flash attention (fp16 MMA) -> g_attnh, g_linv
    flash_kernel<<<dim3(B_ * H_, S_ / 128), 256, fsmem>>>(td);

    // 3. Head-mean weights (fp16 MMA) -> second output
    weights_kernel<<<dim3(S_ / 64, B_, S_ / 64), 128, wsmem>>>(td, wout);

    // 4. Out projection (fp32 output)
    gemm_hf_kernel<false><<<dim3(D_ / 128, T_ / 128), 128, gsmem>>>(
        attnh_p, woh_p, out_b, attnout_p, T_, D_, D_);

    // 5. Residual + LayerNorm
    ln_kernel<<<T_, 256>>>(x, lnw, lnb, out);
}